// round 1
// baseline (speedup 1.0000x reference)
#include <cuda_runtime.h>
#include <math.h>

// Problem constants
#define S_LEN 4096
#define B_SZ  8
#define E_DIM 1024
#define H_NUM 16
#define D_DIM 64
#define K_DIM 64        // proj dim; phi dim = 2K = 128
#define TAU   1.0f
#define NTOK  (S_LEN * B_SZ)          // 32768
#define N2    (2 * E_DIM)             // 2048 (k cols 0..1023, v cols 1024..2047)

// Output layout (flat concat of reference tuple):
//   s  : [B,H,2K,D] = 1048576 floats at offset 0
//   z  : [B,H,2K]   =   16384 floats at offset 1048576
//   rm : [H,K,D]    =   65536 floats at offset 1064960
#define OUT_S_OFF 0
#define OUT_Z_OFF 1048576
#define OUT_RM_OFF 1064960
#define OUT_TOTAL 1130496

// Scratch (device globals; allocation in kernel_launch is forbidden)
__device__ float g_kv[(size_t)NTOK * N2];    // [token][0:1024]=k, [1024:2048]=v   (268 MB)
__device__ float g_phi[(size_t)NTOK * 2048]; // [token][h*128 + kk]                (268 MB)

// ---------------------------------------------------------------------------
// Kernel 0: init output — zero s,z regions; write rm = random_matrices / TAU
// ---------------------------------------------------------------------------
__global__ void init_out_kernel(float* __restrict__ out,
                                const float* __restrict__ rm_in) {
    int i = blockIdx.x * blockDim.x + threadIdx.x;
    if (i < OUT_RM_OFF) {
        out[i] = 0.0f;
    } else if (i < OUT_TOTAL) {
        out[i] = rm_in[i - OUT_RM_OFF] * (1.0f / TAU);
    }
}

// ---------------------------------------------------------------------------
// Kernel 1: fused KV GEMM.  C[t, n] = enc[t,:] . W[n,:] + bias[n]
//   n < 1024 -> Wk/bk ; n >= 1024 -> Wv/bv
//   Classic 128x128x16 tiled SGEMM, 256 threads, 8x8 per-thread microtile.
// ---------------------------------------------------------------------------
#define BM 128
#define BN 128
#define BKK 16

__global__ __launch_bounds__(256) void gemm_kv_kernel(
    const float* __restrict__ A,    // [32768,1024]
    const float* __restrict__ Wk,   // [1024,1024] row = out feature
    const float* __restrict__ bk,
    const float* __restrict__ Wv,
    const float* __restrict__ bv) {
    __shared__ float As[BKK][BM];
    __shared__ float Bs[BKK][BN];

    const int tid = threadIdx.x;
    const int block_n = blockIdx.x * BN;   // 0..2047, tile fully inside Wk or Wv
    const int block_m = blockIdx.y * BM;

    const float* __restrict__ W    = (block_n < E_DIM) ? Wk : Wv;
    const float* __restrict__ bias = (block_n < E_DIM) ? bk : bv;
    const int wn = (block_n < E_DIM) ? block_n : (block_n - E_DIM);

    const int ty = tid >> 4;   // 0..15
    const int tx = tid & 15;   // 0..15

    float acc[8][8];
#pragma unroll
    for (int i = 0; i < 8; i++)
#pragma unroll
        for (int j = 0; j < 8; j++) acc[i][j] = 0.0f;

    for (int k0 = 0; k0 < E_DIM; k0 += BKK) {
        // Load tiles: 128 rows x 16 cols = 512 float4; 2 per thread.
#pragma unroll
        for (int u = 0; u < 2; u++) {
            int f = tid + u * 256;
            int row = f >> 2;
            int c4  = (f & 3) << 2;
            float4 va = *(const float4*)&A[(size_t)(block_m + row) * E_DIM + k0 + c4];
            As[c4 + 0][row] = va.x;
            As[c4 + 1][row] = va.y;
            As[c4 + 2][row] = va.z;
            As[c4 + 3][row] = va.w;
            float4 vb = *(const float4*)&W[(size_t)(wn + row) * E_DIM + k0 + c4];
            Bs[c4 + 0][row] = vb.x;
            Bs[c4 + 1][row] = vb.y;
            Bs[c4 + 2][row] = vb.z;
            Bs[c4 + 3][row] = vb.w;
        }
        __syncthreads();

#pragma unroll
        for (int kk = 0; kk < BKK; kk++) {
            float a[8], b[8];
            *(float4*)&a[0] = *(const float4*)&As[kk][ty * 8];
            *(float4*)&a[4] = *(const float4*)&As[kk][ty * 8 + 4];
            *(float4*)&b[0] = *(const float4*)&Bs[kk][tx * 8];
            *(float4*)&b[4] = *(const float4*)&Bs[kk][tx * 8 + 4];
#pragma unroll
            for (int i = 0; i < 8; i++)
#pragma unroll
                for (int j = 0; j < 8; j++)
                    acc[i][j] = fmaf(a[i], b[j], acc[i][j]);
        }
        __syncthreads();
    }

    // Epilogue: add bias, store
#pragma unroll
    for (int i = 0; i < 8; i++) {
        size_t rowbase = (size_t)(block_m + ty * 8 + i) * N2 + block_n + tx * 8;
#pragma unroll
        for (int j = 0; j < 8; j++) {
            g_kv[rowbase + j] = acc[i][j] + bias[wn + tx * 8 + j];
        }
    }
}

// ---------------------------------------------------------------------------
// Kernel 2: phi.  For each (token t, head h):
//   proj[kk] = sum_d k[t,h,d] * rm[h,kk,d] * (D^-0.5 / TAU^2)
//   phi[t,h,kk]    = sin(proj[kk]) * K^-0.5   (kk < 64)
//   phi[t,h,64+kk] = cos(proj[kk]) * K^-0.5
//   masked tokens -> 0
// Block: 64 tokens x 1 head, 256 threads (8 warps; warp handles 8 tokens,
// each lane computes 2 proj values).
// ---------------------------------------------------------------------------
__global__ __launch_bounds__(256) void phi_kernel(
    const float* __restrict__ rm,           // [16,64,64]  (h,kk,d)
    const unsigned char* __restrict__ mask) // [32768] bool
{
    __shared__ float rms[64][65];  // [d][kk] (padded)
    __shared__ float ks[64][64];   // [tok][d]

    const int tid = threadIdx.x;
    const int h = blockIdx.y;
    const int t0 = blockIdx.x * 64;

    // load rm transposed: rms[d][kk] = rm[h,kk,d]
    for (int i = tid; i < 64 * 64; i += 256) {
        int kk = i >> 6;
        int d = i & 63;
        rms[d][kk] = rm[h * 4096 + i];
    }
    // load k tile
    for (int i = tid; i < 64 * 64; i += 256) {
        int tok = i >> 6;
        int d = i & 63;
        ks[tok][d] = g_kv[(size_t)(t0 + tok) * N2 + h * D_DIM + d];
    }
    __syncthreads();

    const int warp = tid >> 5;
    const int lane = tid & 31;
    const float pscale = (0.125f / (TAU * TAU));  // D^-0.5 / tau^2
    const float kscale = 0.125f;                  // K^-0.5

    for (int tt = warp; tt < 64; tt += 8) {
        float p0 = 0.0f, p1 = 0.0f;
#pragma unroll
        for (int d = 0; d < 64; d++) {
            float kd = ks[tt][d];
            p0 = fmaf(kd, rms[d][lane], p0);
            p1 = fmaf(kd, rms[d][lane + 32], p1);
        }
        p0 *= pscale;
        p1 *= pscale;
        float s0, c0, s1, c1;
        sincosf(p0, &s0, &c0);
        sincosf(p1, &s1, &c1);
        int t = t0 + tt;
        float m = mask[t] ? 0.0f : kscale;
        size_t base = (size_t)t * 2048 + h * 128;
        g_phi[base + lane]      = s0 * m;
        g_phi[base + 32 + lane] = s1 * m;
        g_phi[base + 64 + lane] = c0 * m;
        g_phi[base + 96 + lane] = c1 * m;
    }
}

// ---------------------------------------------------------------------------
// Kernel 3: accumulate s[b,h,kk,d] = sum_s phi[s,b,h,kk]*v[s,b,h,d],
//           z[b,h,kk] = sum_s phi[s,b,h,kk].
// Grid: (chunks=16, bh=128). Each block reduces 256 sequence positions into a
// 128x64 tile in registers (256 threads, 8x4 each), then atomicAdd.
// ---------------------------------------------------------------------------
#define CHUNK 256

__global__ __launch_bounds__(256) void accum_kernel(float* __restrict__ out) {
    __shared__ float ps[16][128];      // phi [srow][kk]
    __shared__ float vs[16][68];       // v   [srow][d]  (padded)

    const int tid = threadIdx.x;
    const int bh = blockIdx.y;         // b*16 + h
    const int b = bh >> 4;
    const int h = bh & 15;
    const int sbeg = blockIdx.x * CHUNK;

    const int ty = tid >> 4;           // 0..15  (kk groups of 8)
    const int tx = tid & 15;           // 0..15  (d groups of 4)

    float acc[8][4];
#pragma unroll
    for (int i = 0; i < 8; i++)
#pragma unroll
        for (int j = 0; j < 4; j++) acc[i][j] = 0.0f;
    float zacc = 0.0f;

    for (int sc = 0; sc < CHUNK; sc += 16) {
        // load phi: 16 x 128
#pragma unroll
        for (int u = 0; u < 8; u++) {
            int i = tid + u * 256;
            int r = i >> 7;
            int c = i & 127;
            size_t t = (size_t)(sbeg + sc + r) * B_SZ + b;
            ps[r][c] = g_phi[t * 2048 + h * 128 + c];
        }
        // load v: 16 x 64
#pragma unroll
        for (int u = 0; u < 4; u++) {
            int i = tid + u * 256;
            int r = i >> 6;
            int c = i & 63;
            size_t t = (size_t)(sbeg + sc + r) * B_SZ + b;
            vs[r][c] = g_kv[t * N2 + E_DIM + h * D_DIM + c];
        }
        __syncthreads();

#pragma unroll
        for (int r = 0; r < 16; r++) {
            float a[8], bb[4];
#pragma unroll
            for (int i = 0; i < 8; i++) a[i] = ps[r][ty * 8 + i];
#pragma unroll
            for (int j = 0; j < 4; j++) bb[j] = vs[r][tx * 4 + j];
#pragma unroll
            for (int i = 0; i < 8; i++)
#pragma unroll
                for (int j = 0; j < 4; j++)
                    acc[i][j] = fmaf(a[i], bb[j], acc[i][j]);
        }
        if (tid < 128) {
#pragma unroll
            for (int r = 0; r < 16; r++) zacc += ps[r][tid];
        }
        __syncthreads();
    }

    // commit
    size_t sbase = (size_t)bh * 128 * 64;
#pragma unroll
    for (int i = 0; i < 8; i++) {
#pragma unroll
        for (int j = 0; j < 4; j++) {
            atomicAdd(&out[OUT_S_OFF + sbase + (size_t)(ty * 8 + i) * 64 + tx * 4 + j],
                      acc[i][j]);
        }
    }
    if (tid < 128) {
        atomicAdd(&out[OUT_Z_OFF + bh * 128 + tid], zacc);
    }
}

// ---------------------------------------------------------------------------
// Launch
// ---------------------------------------------------------------------------
extern "C" void kernel_launch(void* const* d_in, const int* in_sizes, int n_in,
                              void* d_out, int out_size) {
    (void)in_sizes; (void)n_in; (void)out_size;
    const float* enc  = (const float*)d_in[0];
    const float* Wk   = (const float*)d_in[1];
    const float* bk   = (const float*)d_in[2];
    const float* Wv   = (const float*)d_in[3];
    const float* bv   = (const float*)d_in[4];
    const float* rm   = (const float*)d_in[5];
    const unsigned char* mask = (const unsigned char*)d_in[6];
    float* out = (float*)d_out;

    // 0: init output (zero s,z; write rm/tau)
    init_out_kernel<<<(OUT_TOTAL + 255) / 256, 256>>>(out, rm);

    // 1: KV GEMM  (M=32768, N=2048, K=1024)
    dim3 ggrid(N2 / BN, NTOK / BM);
    gemm_kv_kernel<<<ggrid, 256>>>(enc, Wk, bk, Wv, bv);

    // 2: phi
    dim3 pgrid(NTOK / 64, H_NUM);
    phi_kernel<<<pgrid, 256>>>(rm, mask);

    // 3: accumulate s, z
    dim3 agrid(S_LEN / CHUNK, B_SZ * H_NUM);
    accum_kernel<<<agrid, 256>>>(out);
}

// round 4
// speedup vs baseline: 2.5307x; 2.5307x over previous
#include <cuda_runtime.h>
#include <math.h>
#include <stdint.h>

// Problem constants
#define S_LEN 4096
#define B_SZ  8
#define E_DIM 1024
#define H_NUM 16
#define D_DIM 64
#define K_DIM 64
#define TAU   1.0f
#define NTOK  (S_LEN * B_SZ)          // 32768
#define N2    (2 * E_DIM)             // 2048

// Output layout: s [B,H,2K,D] | z [B,H,2K] | rm [H,K,D]
#define OUT_S_OFF 0
#define OUT_Z_OFF 1048576
#define OUT_RM_OFF 1064960
#define OUT_TOTAL 1130496

// Scratch
__device__ float g_kv[(size_t)NTOK * N2];    // [token][0:1024]=k, [1024:2048]=v
__device__ float g_phi[(size_t)NTOK * 2048]; // [token][h*128 + kk]

// ---------------------------------------------------------------------------
// PTX helpers (all arch-agnostic: sm_80-era ops only, legal on compute_103)
// ---------------------------------------------------------------------------
__device__ __forceinline__ uint32_t smem_u32(const void* p) {
    uint32_t a;
    asm("{ .reg .u64 t; cvta.to.shared.u64 t, %1; cvt.u32.u64 %0, t; }" : "=r"(a) : "l"(p));
    return a;
}
__device__ __forceinline__ void cp_async16(uint32_t saddr, const void* g) {
    asm volatile("cp.async.cg.shared.global [%0], [%1], 16;" :: "r"(saddr), "l"(g));
}
__device__ __forceinline__ void cp_commit() { asm volatile("cp.async.commit_group;" ::: "memory"); }
template <int N> __device__ __forceinline__ void cp_wait() {
    asm volatile("cp.async.wait_group %0;" :: "n"(N) : "memory");
}
__device__ __forceinline__ void ldsm_x4(uint32_t& r0, uint32_t& r1, uint32_t& r2, uint32_t& r3,
                                        uint32_t addr) {
    asm volatile("ldmatrix.sync.aligned.m8n8.x4.shared.b16 {%0,%1,%2,%3}, [%4];"
                 : "=r"(r0), "=r"(r1), "=r"(r2), "=r"(r3) : "r"(addr));
}
__device__ __forceinline__ void mma_tf32(float* c, const uint32_t* a, const uint32_t* b) {
    asm volatile(
        "mma.sync.aligned.m16n8k8.row.col.f32.tf32.tf32.f32 "
        "{%0,%1,%2,%3}, {%4,%5,%6,%7}, {%8,%9}, {%0,%1,%2,%3};"
        : "+f"(c[0]), "+f"(c[1]), "+f"(c[2]), "+f"(c[3])
        : "r"(a[0]), "r"(a[1]), "r"(a[2]), "r"(a[3]), "r"(b[0]), "r"(b[1]));
}

// ---------------------------------------------------------------------------
// Kernel 0: init output
// ---------------------------------------------------------------------------
__global__ void init_out_kernel(float* __restrict__ out, const float* __restrict__ rm_in) {
    int i = blockIdx.x * blockDim.x + threadIdx.x;
    if (i < OUT_RM_OFF) {
        out[i] = 0.0f;
    } else if (i < OUT_TOTAL) {
        out[i] = rm_in[i - OUT_RM_OFF] * (1.0f / TAU);
    }
}

// ---------------------------------------------------------------------------
// Kernel 1: KV GEMM via mma.sync tf32 (SM80-style, works on compute_103 base).
//   C[32768, 2048] = enc @ W^T + bias, W row-major [n][k].
//   CTA tile 128x128x32, 3-stage cp.async pipeline, warp tile 32x64.
// ---------------------------------------------------------------------------
#define GBM 128
#define GBN 128
#define GBK 32
#define GSTAGES 3
#define GK_ITERS (E_DIM / GBK)                 // 32
#define G_TILE_BYTES (128 * GBK * 4)           // 16 KB (A or B)
#define G_STAGE_BYTES (2 * G_TILE_BYTES)       // 32 KB
#define G_SMEM_TOTAL (GSTAGES * G_STAGE_BYTES) // 96 KB

// swizzled byte offset inside a [128 rows][32 floats] tile: row r, 16B-chunk c
__device__ __forceinline__ uint32_t tile_off(int r, int c) {
    return (uint32_t)(r * 128 + ((c ^ (r & 7)) << 4));
}

__device__ __forceinline__ void g_load_stage(uint32_t sA, uint32_t sB, int k0,
                                             const float* __restrict__ A,
                                             const float* __restrict__ W,
                                             int m0, int wn0, int tid) {
    const float* ap = A + (size_t)m0 * E_DIM + k0;
    const float* bp = W + (size_t)wn0 * E_DIM + k0;
#pragma unroll
    for (int i = 0; i < 4; i++) {
        int lin = tid + i * 256;
        int r = lin >> 3, c = lin & 7;
        cp_async16(sA + tile_off(r, c), ap + (size_t)r * E_DIM + c * 4);
    }
#pragma unroll
    for (int i = 0; i < 4; i++) {
        int lin = tid + i * 256;
        int r = lin >> 3, c = lin & 7;
        cp_async16(sB + tile_off(r, c), bp + (size_t)r * E_DIM + c * 4);
    }
}

__global__ __launch_bounds__(256) void gemm_kv_mma(
    const float* __restrict__ A,
    const float* __restrict__ Wk, const float* __restrict__ bk,
    const float* __restrict__ Wv, const float* __restrict__ bv) {
    extern __shared__ char smem[];
    const uint32_t sb = smem_u32(smem);

    const int tid = threadIdx.x;
    const int lane = tid & 31;
    const int warp = tid >> 5;
    const int wm = warp & 3;   // 4 warps along M -> 32 rows each
    const int wn = warp >> 2;  // 2 warps along N -> 64 cols each

    const int n0 = blockIdx.x * GBN;  // 0..2047
    const int m0 = blockIdx.y * GBM;
    const float* __restrict__ W    = (n0 < E_DIM) ? Wk : Wv;
    const float* __restrict__ bias = (n0 < E_DIM) ? bk : bv;
    const int wn0 = n0 & (E_DIM - 1);

    float acc[2][8][4];
#pragma unroll
    for (int t = 0; t < 2; t++)
#pragma unroll
        for (int j = 0; j < 8; j++)
#pragma unroll
            for (int q = 0; q < 4; q++) acc[t][j][q] = 0.0f;

    // Prologue: stages 0,1
#pragma unroll
    for (int s = 0; s < GSTAGES - 1; s++) {
        uint32_t base = sb + s * G_STAGE_BYTES;
        g_load_stage(base, base + G_TILE_BYTES, s * GBK, A, W, m0, wn0, tid);
        cp_commit();
    }

    const int mi = lane >> 3;       // ldmatrix sub-matrix this lane addresses
    const int mr = lane & 7;        // row within sub-matrix

    for (int k = 0; k < GK_ITERS; k++) {
        cp_wait<1>();
        __syncthreads();

        const int s = k % GSTAGES;
        const uint32_t sA = sb + s * G_STAGE_BYTES;
        const uint32_t sB = sA + G_TILE_BYTES;

#pragma unroll
        for (int ks = 0; ks < 4; ks++) {
            // A fragments: 2 m-tiles of 16x8
            uint32_t a[2][4];
#pragma unroll
            for (int t = 0; t < 2; t++) {
                int row = wm * 32 + t * 16 + ((mi & 1) << 3) + mr;
                int kc = ks * 2 + (mi >> 1);
                ldsm_x4(a[t][0], a[t][1], a[t][2], a[t][3], sA + tile_off(row, kc));
            }
            // B fragments: 8 n-tiles of 8(n)x8(k); one x4 covers 2 n-tiles
            uint32_t b[8][2];
#pragma unroll
            for (int u = 0; u < 4; u++) {
                int j = 2 * u + (mi >> 1);
                int row = wn * 64 + j * 8 + mr;
                int kc = ks * 2 + (mi & 1);
                ldsm_x4(b[2 * u][0], b[2 * u][1], b[2 * u + 1][0], b[2 * u + 1][1],
                        sB + tile_off(row, kc));
            }
#pragma unroll
            for (int t = 0; t < 2; t++)
#pragma unroll
                for (int j = 0; j < 8; j++)
                    mma_tf32(acc[t][j], a[t], b[j]);
        }

        __syncthreads();
        // Prefetch stage k+2 (or empty commit to keep group accounting uniform)
        int kf = k + GSTAGES - 1;
        if (kf < GK_ITERS) {
            int sf = kf % GSTAGES;
            uint32_t base = sb + sf * G_STAGE_BYTES;
            g_load_stage(base, base + G_TILE_BYTES, kf * GBK, A, W, m0, wn0, tid);
        }
        cp_commit();
    }

    // Epilogue: c0,c1 -> row g cols 2*tig..+1 ; c2,c3 -> row g+8
    const int g = lane >> 2;
    const int tig = lane & 3;
#pragma unroll
    for (int t = 0; t < 2; t++) {
        int row = m0 + wm * 32 + t * 16 + g;
#pragma unroll
        for (int j = 0; j < 8; j++) {
            int colg = n0 + wn * 64 + j * 8 + tig * 2;
            int colw = wn0 + wn * 64 + j * 8 + tig * 2;
            float b0 = bias[colw], b1 = bias[colw + 1];
            float2 v0 = make_float2(acc[t][j][0] + b0, acc[t][j][1] + b1);
            float2 v1 = make_float2(acc[t][j][2] + b0, acc[t][j][3] + b1);
            *(float2*)&g_kv[(size_t)row * N2 + colg] = v0;
            *(float2*)&g_kv[(size_t)(row + 8) * N2 + colg] = v1;
        }
    }
}

// ---------------------------------------------------------------------------
// Kernel 2: phi (random feature map)
// ---------------------------------------------------------------------------
__global__ __launch_bounds__(256) void phi_kernel(
    const float* __restrict__ rm,
    const unsigned char* __restrict__ mask) {
    __shared__ float rms[64][65];
    __shared__ float ks[64][64];

    const int tid = threadIdx.x;
    const int h = blockIdx.y;
    const int t0 = blockIdx.x * 64;

    for (int i = tid; i < 64 * 64; i += 256) {
        int kk = i >> 6;
        int d = i & 63;
        rms[d][kk] = rm[h * 4096 + i];
    }
    for (int i = tid; i < 64 * 64; i += 256) {
        int tok = i >> 6;
        int d = i & 63;
        ks[tok][d] = g_kv[(size_t)(t0 + tok) * N2 + h * D_DIM + d];
    }
    __syncthreads();

    const int warp = tid >> 5;
    const int lane = tid & 31;
    const float pscale = (0.125f / (TAU * TAU));
    const float kscale = 0.125f;

    for (int tt = warp; tt < 64; tt += 8) {
        float p0 = 0.0f, p1 = 0.0f;
#pragma unroll
        for (int d = 0; d < 64; d++) {
            float kd = ks[tt][d];
            p0 = fmaf(kd, rms[d][lane], p0);
            p1 = fmaf(kd, rms[d][lane + 32], p1);
        }
        p0 *= pscale;
        p1 *= pscale;
        float s0, c0, s1, c1;
        sincosf(p0, &s0, &c0);
        sincosf(p1, &s1, &c1);
        int t = t0 + tt;
        float m = mask[t] ? 0.0f : kscale;
        size_t base = (size_t)t * 2048 + h * 128;
        g_phi[base + lane]      = s0 * m;
        g_phi[base + 32 + lane] = s1 * m;
        g_phi[base + 64 + lane] = c0 * m;
        g_phi[base + 96 + lane] = c1 * m;
    }
}

// ---------------------------------------------------------------------------
// Kernel 3: accumulate s, z
// ---------------------------------------------------------------------------
#define CHUNK 256

__global__ __launch_bounds__(256) void accum_kernel(float* __restrict__ out) {
    __shared__ float ps[16][128];
    __shared__ float vs[16][68];

    const int tid = threadIdx.x;
    const int bh = blockIdx.y;
    const int b = bh >> 4;
    const int h = bh & 15;
    const int sbeg = blockIdx.x * CHUNK;

    const int ty = tid >> 4;
    const int tx = tid & 15;

    float acc[8][4];
#pragma unroll
    for (int i = 0; i < 8; i++)
#pragma unroll
        for (int j = 0; j < 4; j++) acc[i][j] = 0.0f;
    float zacc = 0.0f;

    for (int sc = 0; sc < CHUNK; sc += 16) {
#pragma unroll
        for (int u = 0; u < 8; u++) {
            int i = tid + u * 256;
            int r = i >> 7;
            int c = i & 127;
            size_t t = (size_t)(sbeg + sc + r) * B_SZ + b;
            ps[r][c] = g_phi[t * 2048 + h * 128 + c];
        }
#pragma unroll
        for (int u = 0; u < 4; u++) {
            int i = tid + u * 256;
            int r = i >> 6;
            int c = i & 63;
            size_t t = (size_t)(sbeg + sc + r) * B_SZ + b;
            vs[r][c] = g_kv[t * N2 + E_DIM + h * D_DIM + c];
        }
        __syncthreads();

#pragma unroll
        for (int r = 0; r < 16; r++) {
            float a[8], bb[4];
#pragma unroll
            for (int i = 0; i < 8; i++) a[i] = ps[r][ty * 8 + i];
#pragma unroll
            for (int j = 0; j < 4; j++) bb[j] = vs[r][tx * 4 + j];
#pragma unroll
            for (int i = 0; i < 8; i++)
#pragma unroll
                for (int j = 0; j < 4; j++)
                    acc[i][j] = fmaf(a[i], bb[j], acc[i][j]);
        }
        if (tid < 128) {
#pragma unroll
            for (int r = 0; r < 16; r++) zacc += ps[r][tid];
        }
        __syncthreads();
    }

    size_t sbase = (size_t)bh * 128 * 64;
#pragma unroll
    for (int i = 0; i < 8; i++) {
#pragma unroll
        for (int j = 0; j < 4; j++) {
            atomicAdd(&out[OUT_S_OFF + sbase + (size_t)(ty * 8 + i) * 64 + tx * 4 + j],
                      acc[i][j]);
        }
    }
    if (tid < 128) {
        atomicAdd(&out[OUT_Z_OFF + bh * 128 + tid], zacc);
    }
}

// ---------------------------------------------------------------------------
// Launch
// ---------------------------------------------------------------------------
extern "C" void kernel_launch(void* const* d_in, const int* in_sizes, int n_in,
                              void* d_out, int out_size) {
    (void)in_sizes; (void)n_in; (void)out_size;
    const float* enc  = (const float*)d_in[0];
    const float* Wk   = (const float*)d_in[1];
    const float* bk   = (const float*)d_in[2];
    const float* Wv   = (const float*)d_in[3];
    const float* bv   = (const float*)d_in[4];
    const float* rm   = (const float*)d_in[5];
    const unsigned char* mask = (const unsigned char*)d_in[6];
    float* out = (float*)d_out;

    cudaFuncSetAttribute(gemm_kv_mma, cudaFuncAttributeMaxDynamicSharedMemorySize, G_SMEM_TOTAL);

    init_out_kernel<<<(OUT_TOTAL + 255) / 256, 256>>>(out, rm);

    dim3 ggrid(N2 / GBN, NTOK / GBM);   // (16, 256); x = n fastest for A reuse in L2
    gemm_kv_mma<<<ggrid, 256, G_SMEM_TOTAL>>>(enc, Wk, bk, Wv, bv);

    dim3 pgrid(NTOK / 64, H_NUM);
    phi_kernel<<<pgrid, 256>>>(rm, mask);

    dim3 agrid(S_LEN / CHUNK, B_SZ * H_NUM);
    accum_kernel<<<agrid, 256>>>(out);
}

// round 6
// speedup vs baseline: 4.5752x; 1.8079x over previous
#include <cuda_runtime.h>
#include <math.h>
#include <stdint.h>

// Problem constants
#define S_LEN 4096
#define B_SZ  8
#define E_DIM 1024
#define H_NUM 16
#define D_DIM 64
#define K_DIM 64
#define TAU   1.0f
#define NTOK  (S_LEN * B_SZ)          // 32768
#define N2    (2 * E_DIM)             // 2048

// Output layout: s [B,H,2K,D] | z [B,H,2K] | rm [H,K,D]
#define OUT_S_OFF 0
#define OUT_Z_OFF 1048576
#define OUT_RM_OFF 1064960
#define OUT_TOTAL 1130496

// Scratch
__device__ float g_phi[(size_t)NTOK * 2048]; // [t][h*128 + kk]  (268 MB)
__device__ float g_v[(size_t)NTOK * 1024];   // [t][h*64 + d]    (134 MB)
__device__ float g_wproj[E_DIM * E_DIM];     // folded rm@Wk  [h*64+kk][e]
__device__ float g_bproj[E_DIM];             // folded rm@bk

// ---------------------------------------------------------------------------
// PTX helpers (arch-agnostic for compute_103 base)
// ---------------------------------------------------------------------------
__device__ __forceinline__ uint32_t smem_u32(const void* p) {
    uint32_t a;
    asm("{ .reg .u64 t; cvta.to.shared.u64 t, %1; cvt.u32.u64 %0, t; }" : "=r"(a) : "l"(p));
    return a;
}
__device__ __forceinline__ void cp_async16(uint32_t saddr, const void* g) {
    asm volatile("cp.async.cg.shared.global [%0], [%1], 16;" :: "r"(saddr), "l"(g));
}
__device__ __forceinline__ void cp_commit() { asm volatile("cp.async.commit_group;" ::: "memory"); }
template <int N> __device__ __forceinline__ void cp_wait() {
    asm volatile("cp.async.wait_group %0;" :: "n"(N) : "memory");
}
__device__ __forceinline__ void ldsm_x4(uint32_t& r0, uint32_t& r1, uint32_t& r2, uint32_t& r3,
                                        uint32_t addr) {
    asm volatile("ldmatrix.sync.aligned.m8n8.x4.shared.b16 {%0,%1,%2,%3}, [%4];"
                 : "=r"(r0), "=r"(r1), "=r"(r2), "=r"(r3) : "r"(addr));
}
__device__ __forceinline__ void mma_tf32(float* c, const uint32_t* a, const uint32_t* b) {
    asm volatile(
        "mma.sync.aligned.m16n8k8.row.col.f32.tf32.tf32.f32 "
        "{%0,%1,%2,%3}, {%4,%5,%6,%7}, {%8,%9}, {%0,%1,%2,%3};"
        : "+f"(c[0]), "+f"(c[1]), "+f"(c[2]), "+f"(c[3])
        : "r"(a[0]), "r"(a[1]), "r"(a[2]), "r"(a[3]), "r"(b[0]), "r"(b[1]));
}
// packed fp32x2 fma: c = a*b + c (two independent fp32 lanes, exact fp32 numerics)
__device__ __forceinline__ void ffma2(unsigned long long& c, unsigned long long a,
                                      unsigned long long b) {
    asm("fma.rn.f32x2 %0, %1, %2, %0;" : "+l"(c) : "l"(a), "l"(b));
}
__device__ __forceinline__ unsigned long long dup2(float x) {
    unsigned long long r;
    asm("mov.b64 %0, {%1, %1};" : "=l"(r) : "r"(__float_as_uint(x)));
    return r;
}
__device__ __forceinline__ void unpack2(unsigned long long v, float& lo, float& hi) {
    uint32_t a, b;
    asm("mov.b64 {%0, %1}, %2;" : "=r"(a), "=r"(b) : "l"(v));
    lo = __uint_as_float(a);
    hi = __uint_as_float(b);
}

// ---------------------------------------------------------------------------
// Kernel 0: init output — zero s,z; write rm/tau
// ---------------------------------------------------------------------------
__global__ void init_out_kernel(float* __restrict__ out, const float* __restrict__ rm_in) {
    int i = blockIdx.x * blockDim.x + threadIdx.x;
    if (i < OUT_RM_OFF) {
        out[i] = 0.0f;
    } else if (i < OUT_TOTAL) {
        out[i] = rm_in[i - OUT_RM_OFF] * (1.0f / TAU);
    }
}

// ---------------------------------------------------------------------------
// Kernel F: fold rm into Wk ->  Wproj[h*64+kk][e] = pscale * sum_d Wk[h*64+d][e]*rm[h,kk,d]
//           bproj[h*64+kk]   = pscale * sum_d bk[h*64+d]*rm[h,kk,d]
// grid (h=16, echunk=16), 256 threads; fp32 exact.
// ---------------------------------------------------------------------------
__global__ __launch_bounds__(256) void fold_kernel(
    const float* __restrict__ Wk, const float* __restrict__ bk,
    const float* __restrict__ rm) {
    __shared__ float rs[64][65];   // [kk][d]
    __shared__ float wks[64][65];  // [d][e]

    const int tid = threadIdx.x;
    const int h = blockIdx.x;
    const int e0 = blockIdx.y * 64;
    const float pscale = (0.125f / (TAU * TAU));   // D^-0.5 / tau^2

#pragma unroll
    for (int u = 0; u < 16; u++) {
        int i = tid + u * 256;
        rs[i >> 6][i & 63] = rm[h * 4096 + i];
    }
#pragma unroll
    for (int u = 0; u < 16; u++) {
        int i = tid + u * 256;
        int d = i >> 6, e = i & 63;
        wks[d][e] = Wk[(size_t)(h * 64 + d) * E_DIM + e0 + e];
    }
    __syncthreads();

    const int ty = tid >> 4;   // kk group of 4
    const int tx = tid & 15;   // e group of 4
    float acc[4][4];
#pragma unroll
    for (int i = 0; i < 4; i++)
#pragma unroll
        for (int j = 0; j < 4; j++) acc[i][j] = 0.0f;
#pragma unroll
    for (int d = 0; d < 64; d++) {
        float a[4], b[4];
#pragma unroll
        for (int i = 0; i < 4; i++) a[i] = rs[ty * 4 + i][d];
#pragma unroll
        for (int j = 0; j < 4; j++) b[j] = wks[d][tx * 4 + j];
#pragma unroll
        for (int i = 0; i < 4; i++)
#pragma unroll
            for (int j = 0; j < 4; j++) acc[i][j] = fmaf(a[i], b[j], acc[i][j]);
    }
#pragma unroll
    for (int i = 0; i < 4; i++)
#pragma unroll
        for (int j = 0; j < 4; j++)
            g_wproj[(size_t)(h * 64 + ty * 4 + i) * E_DIM + e0 + tx * 4 + j] =
                acc[i][j] * pscale;

    if (blockIdx.y == 0 && tid < 64) {
        float s = 0.0f;
#pragma unroll
        for (int d = 0; d < 64; d++) s = fmaf(rs[tid][d], bk[h * 64 + d], s);
        g_bproj[h * 64 + tid] = s * pscale;
    }
}

// ---------------------------------------------------------------------------
// Kernel 1: fused GEMM on tf32 mma.sync.
//   cols 0..1023   : proj = enc @ Wproj^T + bproj  -> sin/cos epilogue -> g_phi
//   cols 1024..2047: v    = enc @ Wv^T    + bv     -> g_v
//   CTA tile 128x128x32, 3-stage cp.async, single syncthreads per k-iter.
// ---------------------------------------------------------------------------
#define GBM 128
#define GBN 128
#define GBK 32
#define GSTAGES 3
#define GK_ITERS (E_DIM / GBK)                 // 32
#define G_TILE_BYTES (128 * GBK * 4)           // 16 KB
#define G_STAGE_BYTES (2 * G_TILE_BYTES)       // 32 KB
#define G_SMEM_TOTAL (GSTAGES * G_STAGE_BYTES) // 96 KB

__device__ __forceinline__ uint32_t tile_off(int r, int c) {
    return (uint32_t)(r * 128 + ((c ^ (r & 7)) << 4));
}

__device__ __forceinline__ void g_load_stage(uint32_t sA, uint32_t sB, int k0,
                                             const float* __restrict__ A,
                                             const float* __restrict__ W,
                                             int m0, int wn0, int tid) {
    const float* ap = A + (size_t)m0 * E_DIM + k0;
    const float* bp = W + (size_t)wn0 * E_DIM + k0;
#pragma unroll
    for (int i = 0; i < 4; i++) {
        int lin = tid + i * 256;
        int r = lin >> 3, c = lin & 7;
        cp_async16(sA + tile_off(r, c), ap + (size_t)r * E_DIM + c * 4);
    }
#pragma unroll
    for (int i = 0; i < 4; i++) {
        int lin = tid + i * 256;
        int r = lin >> 3, c = lin & 7;
        cp_async16(sB + tile_off(r, c), bp + (size_t)r * E_DIM + c * 4);
    }
}

__global__ __launch_bounds__(256) void gemm_fused(
    const float* __restrict__ A,
    const float* __restrict__ Wv, const float* __restrict__ bv,
    const unsigned char* __restrict__ mask) {
    extern __shared__ char smem[];
    const uint32_t sb = smem_u32(smem);

    const int tid = threadIdx.x;
    const int lane = tid & 31;
    const int warp = tid >> 5;
    const int wm = warp & 3;
    const int wn = warp >> 2;

    const int n0 = blockIdx.x * GBN;
    const int m0 = blockIdx.y * GBM;
    const bool is_proj = (n0 < E_DIM);
    const float* __restrict__ W = is_proj ? g_wproj : Wv;
    const int wn0 = n0 & (E_DIM - 1);

    float acc[2][8][4];
#pragma unroll
    for (int t = 0; t < 2; t++)
#pragma unroll
        for (int j = 0; j < 8; j++)
#pragma unroll
            for (int q = 0; q < 4; q++) acc[t][j][q] = 0.0f;

#pragma unroll
    for (int s = 0; s < GSTAGES - 1; s++) {
        uint32_t base = sb + s * G_STAGE_BYTES;
        g_load_stage(base, base + G_TILE_BYTES, s * GBK, A, W, m0, wn0, tid);
        cp_commit();
    }

    const int mi = lane >> 3;
    const int mr = lane & 7;

    for (int k = 0; k < GK_ITERS; k++) {
        cp_wait<1>();
        __syncthreads();

        // Prefetch k+2 after barrier: stage (k+2)%3 was stage k-1, drained by
        // this barrier (all warps finished compute(k-1) before arriving).
        int kf = k + 2;
        if (kf < GK_ITERS) {
            int sf = kf % GSTAGES;
            uint32_t base = sb + sf * G_STAGE_BYTES;
            g_load_stage(base, base + G_TILE_BYTES, kf * GBK, A, W, m0, wn0, tid);
        }
        cp_commit();

        const int s = k % GSTAGES;
        const uint32_t sA = sb + s * G_STAGE_BYTES;
        const uint32_t sB = sA + G_TILE_BYTES;

#pragma unroll
        for (int ks = 0; ks < 4; ks++) {
            uint32_t a[2][4];
#pragma unroll
            for (int t = 0; t < 2; t++) {
                int row = wm * 32 + t * 16 + ((mi & 1) << 3) + mr;
                int kc = ks * 2 + (mi >> 1);
                ldsm_x4(a[t][0], a[t][1], a[t][2], a[t][3], sA + tile_off(row, kc));
            }
            uint32_t b[8][2];
#pragma unroll
            for (int u = 0; u < 4; u++) {
                int j = 2 * u + (mi >> 1);
                int row = wn * 64 + j * 8 + mr;
                int kc = ks * 2 + (mi & 1);
                ldsm_x4(b[2 * u][0], b[2 * u][1], b[2 * u + 1][0], b[2 * u + 1][1],
                        sB + tile_off(row, kc));
            }
#pragma unroll
            for (int t = 0; t < 2; t++)
#pragma unroll
                for (int j = 0; j < 8; j++)
                    mma_tf32(acc[t][j], a[t], b[j]);
        }
    }

    // Epilogue
    const int g = lane >> 2;
    const int tig = lane & 3;
    if (is_proj) {
#pragma unroll
        for (int t = 0; t < 2; t++) {
            int row0 = m0 + wm * 32 + t * 16 + g;
            float mv0 = mask[row0] ? 0.0f : 0.125f;        // K^-0.5
            float mv1 = mask[row0 + 8] ? 0.0f : 0.125f;
#pragma unroll
            for (int j = 0; j < 8; j++) {
                int col = n0 + wn * 64 + j * 8 + tig * 2;
                int h = col >> 6, kk = col & 63;
                float b0 = g_bproj[col], b1 = g_bproj[col + 1];
                float p00 = acc[t][j][0] + b0, p01 = acc[t][j][1] + b1;
                float p10 = acc[t][j][2] + b0, p11 = acc[t][j][3] + b1;
                float s00, c00, s01, c01, s10, c10, s11, c11;
                sincosf(p00, &s00, &c00);
                sincosf(p01, &s01, &c01);
                sincosf(p10, &s10, &c10);
                sincosf(p11, &s11, &c11);
                size_t base0 = (size_t)row0 * 2048 + h * 128 + kk;
                size_t base1 = (size_t)(row0 + 8) * 2048 + h * 128 + kk;
                *(float2*)&g_phi[base0]      = make_float2(s00 * mv0, s01 * mv0);
                *(float2*)&g_phi[base0 + 64] = make_float2(c00 * mv0, c01 * mv0);
                *(float2*)&g_phi[base1]      = make_float2(s10 * mv1, s11 * mv1);
                *(float2*)&g_phi[base1 + 64] = make_float2(c10 * mv1, c11 * mv1);
            }
        }
    } else {
#pragma unroll
        for (int t = 0; t < 2; t++) {
            int row0 = m0 + wm * 32 + t * 16 + g;
#pragma unroll
            for (int j = 0; j < 8; j++) {
                int colw = wn0 + wn * 64 + j * 8 + tig * 2;
                float b0 = bv[colw], b1 = bv[colw + 1];
                float2 v0 = make_float2(acc[t][j][0] + b0, acc[t][j][1] + b1);
                float2 v1 = make_float2(acc[t][j][2] + b0, acc[t][j][3] + b1);
                *(float2*)&g_v[(size_t)row0 * 1024 + colw] = v0;
                *(float2*)&g_v[(size_t)(row0 + 8) * 1024 + colw] = v1;
            }
        }
    }
}

// ---------------------------------------------------------------------------
// Kernel 3: accumulate s, z — fp32x2 packed FFMA (exact fp32 numerics).
//   acc2[p][j] packs (kk = ty*8+2p, kk+1) x (d = tx*4+j).
// ---------------------------------------------------------------------------
#define CHUNK 256

__global__ __launch_bounds__(256) void accum_kernel(float* __restrict__ out) {
    __shared__ float ps[16][128];
    __shared__ float vs[16][68];

    const int tid = threadIdx.x;
    const int bh = blockIdx.y;
    const int b = bh >> 4;
    const int h = bh & 15;
    const int sbeg = blockIdx.x * CHUNK;

    const int ty = tid >> 4;
    const int tx = tid & 15;

    unsigned long long acc2[4][4];
#pragma unroll
    for (int p = 0; p < 4; p++)
#pragma unroll
        for (int j = 0; j < 4; j++) acc2[p][j] = 0ull;
    float zacc = 0.0f;

    for (int sc = 0; sc < CHUNK; sc += 16) {
        // stage phi 16x128 (float4) and v 16x64 (float4)
#pragma unroll
        for (int u = 0; u < 2; u++) {
            int i = tid + u * 256;
            int r = i >> 5, c4 = i & 31;
            size_t t = (size_t)(sbeg + sc + r) * B_SZ + b;
            *(float4*)&ps[r][c4 * 4] = *(const float4*)&g_phi[t * 2048 + h * 128 + c4 * 4];
        }
        {
            int r = tid >> 4, c4 = tid & 15;
            size_t t = (size_t)(sbeg + sc + r) * B_SZ + b;
            *(float4*)&vs[r][c4 * 4] = *(const float4*)&g_v[t * 1024 + h * 64 + c4 * 4];
        }
        __syncthreads();

#pragma unroll
        for (int r = 0; r < 16; r++) {
            unsigned long long a2[4];
#pragma unroll
            for (int p = 0; p < 4; p++)
                a2[p] = *(const unsigned long long*)&ps[r][ty * 8 + 2 * p];
            float4 bv4 = *(const float4*)&vs[r][tx * 4];
            unsigned long long bd[4];
            bd[0] = dup2(bv4.x); bd[1] = dup2(bv4.y);
            bd[2] = dup2(bv4.z); bd[3] = dup2(bv4.w);
#pragma unroll
            for (int p = 0; p < 4; p++)
#pragma unroll
                for (int j = 0; j < 4; j++)
                    ffma2(acc2[p][j], a2[p], bd[j]);
        }
        if (tid < 128) {
#pragma unroll
            for (int r = 0; r < 16; r++) zacc += ps[r][tid];
        }
        __syncthreads();
    }

    size_t sbase = (size_t)bh * 128 * 64;
#pragma unroll
    for (int p = 0; p < 4; p++) {
        int kk0 = ty * 8 + 2 * p;
#pragma unroll
        for (int j = 0; j < 4; j++) {
            float lo, hi;
            unpack2(acc2[p][j], lo, hi);
            atomicAdd(&out[OUT_S_OFF + sbase + (size_t)kk0 * 64 + tx * 4 + j], lo);
            atomicAdd(&out[OUT_S_OFF + sbase + (size_t)(kk0 + 1) * 64 + tx * 4 + j], hi);
        }
    }
    if (tid < 128) {
        atomicAdd(&out[OUT_Z_OFF + bh * 128 + tid], zacc);
    }
}

// ---------------------------------------------------------------------------
// Launch
// ---------------------------------------------------------------------------
extern "C" void kernel_launch(void* const* d_in, const int* in_sizes, int n_in,
                              void* d_out, int out_size) {
    (void)in_sizes; (void)n_in; (void)out_size;
    const float* enc  = (const float*)d_in[0];
    const float* Wk   = (const float*)d_in[1];
    const float* bk   = (const float*)d_in[2];
    const float* Wv   = (const float*)d_in[3];
    const float* bv   = (const float*)d_in[4];
    const float* rm   = (const float*)d_in[5];
    const unsigned char* mask = (const unsigned char*)d_in[6];
    float* out = (float*)d_out;

    cudaFuncSetAttribute(gemm_fused, cudaFuncAttributeMaxDynamicSharedMemorySize, G_SMEM_TOTAL);

    init_out_kernel<<<(OUT_TOTAL + 255) / 256, 256>>>(out, rm);

    dim3 fgrid(H_NUM, E_DIM / 64);  // (16,16)
    fold_kernel<<<fgrid, 256>>>(Wk, bk, rm);

    dim3 ggrid(N2 / GBN, NTOK / GBM);   // (16, 256)
    gemm_fused<<<ggrid, 256, G_SMEM_TOTAL>>>(enc, Wv, bv, mask);

    dim3 agrid(S_LEN / CHUNK, B_SZ * H_NUM);
    accum_kernel<<<agrid, 256>>>(out);
}

// round 10
// speedup vs baseline: 5.8390x; 1.2762x over previous
#include <cuda_runtime.h>
#include <cuda_fp16.h>
#include <math.h>
#include <stdint.h>

// Problem constants
#define S_LEN 4096
#define B_SZ  8
#define E_DIM 1024
#define H_NUM 16
#define D_DIM 64
#define K_DIM 64
#define TAU   1.0f
#define NTOK  (S_LEN * B_SZ)          // 32768
#define N2    (2 * E_DIM)             // 2048

// Output layout: s [B,H,2K,D] | z [B,H,2K] | rm [H,K,D]
#define OUT_S_OFF 0
#define OUT_Z_OFF 1048576
#define OUT_RM_OFF 1064960
#define OUT_TOTAL 1130496

// Scratch
__device__ float  g_phi[(size_t)NTOK * 2048]; // [t][h*128 + kk]  (268 MB)
__device__ float  g_v[(size_t)NTOK * 1024];   // [t][h*64 + d]    (134 MB)
__device__ __half g_a16[(size_t)NTOK * E_DIM];   // enc in fp16 (67 MB)
__device__ __half g_wp16[E_DIM * E_DIM];         // folded rm@Wk, fp16
__device__ __half g_wv16[E_DIM * E_DIM];         // Wv in fp16
__device__ float  g_bproj[E_DIM];                // folded rm@bk (fp32)

// ---------------------------------------------------------------------------
// PTX helpers (arch-agnostic for compute_103 base)
// ---------------------------------------------------------------------------
__device__ __forceinline__ uint32_t smem_u32(const void* p) {
    uint32_t a;
    asm("{ .reg .u64 t; cvta.to.shared.u64 t, %1; cvt.u32.u64 %0, t; }" : "=r"(a) : "l"(p));
    return a;
}
__device__ __forceinline__ void cp_async16(uint32_t saddr, const void* g) {
    asm volatile("cp.async.cg.shared.global [%0], [%1], 16;" :: "r"(saddr), "l"(g));
}
__device__ __forceinline__ void cp_commit() { asm volatile("cp.async.commit_group;" ::: "memory"); }
template <int N> __device__ __forceinline__ void cp_wait() {
    asm volatile("cp.async.wait_group %0;" :: "n"(N) : "memory");
}
__device__ __forceinline__ void ldsm_x4(uint32_t& r0, uint32_t& r1, uint32_t& r2, uint32_t& r3,
                                        uint32_t addr) {
    asm volatile("ldmatrix.sync.aligned.m8n8.x4.shared.b16 {%0,%1,%2,%3}, [%4];"
                 : "=r"(r0), "=r"(r1), "=r"(r2), "=r"(r3) : "r"(addr));
}
__device__ __forceinline__ void mma_f16(float* c, const uint32_t* a, const uint32_t* b) {
    asm volatile(
        "mma.sync.aligned.m16n8k16.row.col.f32.f16.f16.f32 "
        "{%0,%1,%2,%3}, {%4,%5,%6,%7}, {%8,%9}, {%0,%1,%2,%3};"
        : "+f"(c[0]), "+f"(c[1]), "+f"(c[2]), "+f"(c[3])
        : "r"(a[0]), "r"(a[1]), "r"(a[2]), "r"(a[3]), "r"(b[0]), "r"(b[1]));
}
// packed fp32x2 fma (exact fp32 numerics, 2 lanes/instr)
__device__ __forceinline__ void ffma2(unsigned long long& c, unsigned long long a,
                                      unsigned long long b) {
    asm("fma.rn.f32x2 %0, %1, %2, %0;" : "+l"(c) : "l"(a), "l"(b));
}
__device__ __forceinline__ unsigned long long dup2(float x) {
    unsigned long long r;
    asm("mov.b64 %0, {%1, %1};" : "=l"(r) : "r"(__float_as_uint(x)));
    return r;
}
__device__ __forceinline__ void unpack2(unsigned long long v, float& lo, float& hi) {
    uint32_t a, b;
    asm("mov.b64 {%0, %1}, %2;" : "=r"(a), "=r"(b) : "l"(v));
    lo = __uint_as_float(a);
    hi = __uint_as_float(b);
}

// ---------------------------------------------------------------------------
// Kernel 0: init output — zero s,z; write rm/tau
// ---------------------------------------------------------------------------
__global__ void init_out_kernel(float* __restrict__ out, const float* __restrict__ rm_in) {
    int i = blockIdx.x * blockDim.x + threadIdx.x;
    if (i < OUT_RM_OFF) {
        out[i] = 0.0f;
    } else if (i < OUT_TOTAL) {
        out[i] = rm_in[i - OUT_RM_OFF] * (1.0f / TAU);
    }
}

// ---------------------------------------------------------------------------
// Kernel C: fp32 -> fp16 convert into a __device__ symbol (dst selector:
// 0 = g_a16, 1 = g_wv16). 8 elems/thread/iter, 16B ld/st.
// ---------------------------------------------------------------------------
__global__ void convert_f16_kernel(const float* __restrict__ src, int which, int n8) {
    __half* dst = (which == 0) ? g_a16 : g_wv16;
    int stride = gridDim.x * blockDim.x;
    for (int i = blockIdx.x * blockDim.x + threadIdx.x; i < n8; i += stride) {
        const float4* s = (const float4*)(src + (size_t)i * 8);
        float4 v0 = s[0], v1 = s[1];
        __half2 h0 = __floats2half2_rn(v0.x, v0.y);
        __half2 h1 = __floats2half2_rn(v0.z, v0.w);
        __half2 h2 = __floats2half2_rn(v1.x, v1.y);
        __half2 h3 = __floats2half2_rn(v1.z, v1.w);
        uint4 pack;
        pack.x = *(uint32_t*)&h0;
        pack.y = *(uint32_t*)&h1;
        pack.z = *(uint32_t*)&h2;
        pack.w = *(uint32_t*)&h3;
        *(uint4*)(dst + (size_t)i * 8) = pack;
    }
}

// ---------------------------------------------------------------------------
// Kernel F: fold rm into Wk -> fp16 Wproj; fp32 bproj.
//   Wproj[h*64+kk][e] = pscale * sum_d Wk[h*64+d][e] * rm[h,kk,d]
// ---------------------------------------------------------------------------
__global__ __launch_bounds__(256) void fold_kernel(
    const float* __restrict__ Wk, const float* __restrict__ bk,
    const float* __restrict__ rm) {
    __shared__ float rs[64][65];   // [kk][d]
    __shared__ float wks[64][65];  // [d][e]

    const int tid = threadIdx.x;
    const int h = blockIdx.x;
    const int e0 = blockIdx.y * 64;
    const float pscale = (0.125f / (TAU * TAU));

#pragma unroll
    for (int u = 0; u < 16; u++) {
        int i = tid + u * 256;
        rs[i >> 6][i & 63] = rm[h * 4096 + i];
    }
#pragma unroll
    for (int u = 0; u < 16; u++) {
        int i = tid + u * 256;
        int d = i >> 6, e = i & 63;
        wks[d][e] = Wk[(size_t)(h * 64 + d) * E_DIM + e0 + e];
    }
    __syncthreads();

    const int ty = tid >> 4;
    const int tx = tid & 15;
    float acc[4][4];
#pragma unroll
    for (int i = 0; i < 4; i++)
#pragma unroll
        for (int j = 0; j < 4; j++) acc[i][j] = 0.0f;
#pragma unroll
    for (int d = 0; d < 64; d++) {
        float a[4], b[4];
#pragma unroll
        for (int i = 0; i < 4; i++) a[i] = rs[ty * 4 + i][d];
#pragma unroll
        for (int j = 0; j < 4; j++) b[j] = wks[d][tx * 4 + j];
#pragma unroll
        for (int i = 0; i < 4; i++)
#pragma unroll
            for (int j = 0; j < 4; j++) acc[i][j] = fmaf(a[i], b[j], acc[i][j]);
    }
#pragma unroll
    for (int i = 0; i < 4; i++)
#pragma unroll
        for (int j = 0; j < 4; j++)
            g_wp16[(size_t)(h * 64 + ty * 4 + i) * E_DIM + e0 + tx * 4 + j] =
                __float2half_rn(acc[i][j] * pscale);

    if (blockIdx.y == 0 && tid < 64) {
        float s = 0.0f;
#pragma unroll
        for (int d = 0; d < 64; d++) s = fmaf(rs[tid][d], bk[h * 64 + d], s);
        g_bproj[h * 64 + tid] = s * pscale;
    }
}

// ---------------------------------------------------------------------------
// Kernel 1: fused GEMM on fp16 m16n8k16 mma.sync.
//   cols 0..1023   : proj = enc16 @ Wp16^T + bproj -> sin/cos -> g_phi (fp32)
//   cols 1024..2047: v    = enc16 @ Wv16^T + bv    -> g_v (fp32)
//   CTA 128x128x32, 4-stage cp.async, fp16 tiles (64B rows, XOR swizzle).
// ---------------------------------------------------------------------------
#define GBM 128
#define GBN 128
#define GBK 32
#define GSTAGES 4
#define GK_ITERS (E_DIM / GBK)                 // 32
#define G_TILE_BYTES (128 * GBK * 2)           // 8 KB (fp16)
#define G_STAGE_BYTES (2 * G_TILE_BYTES)       // 16 KB
#define G_SMEM_TOTAL (GSTAGES * G_STAGE_BYTES) // 64 KB

// byte offset in a [128 rows][32 fp16] tile; c = 16B chunk (0..3)
__device__ __forceinline__ uint32_t tile_off16(int r, int c) {
    return (uint32_t)(r * 64 + ((c ^ ((r >> 1) & 3)) << 4));
}

__device__ __forceinline__ void g_load_stage(uint32_t sA, uint32_t sB, int k0,
                                             const __half* __restrict__ A,
                                             const __half* __restrict__ W,
                                             int m0, int wn0, int tid) {
    const __half* ap = A + (size_t)m0 * E_DIM + k0;
    const __half* bp = W + (size_t)wn0 * E_DIM + k0;
#pragma unroll
    for (int i = 0; i < 2; i++) {
        int lin = tid + i * 256;
        int r = lin >> 2, c = lin & 3;
        cp_async16(sA + tile_off16(r, c), ap + (size_t)r * E_DIM + c * 8);
    }
#pragma unroll
    for (int i = 0; i < 2; i++) {
        int lin = tid + i * 256;
        int r = lin >> 2, c = lin & 3;
        cp_async16(sB + tile_off16(r, c), bp + (size_t)r * E_DIM + c * 8);
    }
}

__global__ __launch_bounds__(256) void gemm_fused(
    const float* __restrict__ bv,
    const unsigned char* __restrict__ mask) {
    extern __shared__ char smem[];
    const uint32_t sb = smem_u32(smem);

    const int tid = threadIdx.x;
    const int lane = tid & 31;
    const int warp = tid >> 5;
    const int wm = warp & 3;   // 4 warps along M (32 rows each)
    const int wn = warp >> 2;  // 2 warps along N (64 cols each)

    const int n0 = blockIdx.x * GBN;
    const int m0 = blockIdx.y * GBM;
    const bool is_proj = (n0 < E_DIM);
    const __half* __restrict__ W = is_proj ? g_wp16 : g_wv16;
    const int wn0 = n0 & (E_DIM - 1);

    float acc[2][8][4];
#pragma unroll
    for (int t = 0; t < 2; t++)
#pragma unroll
        for (int j = 0; j < 8; j++)
#pragma unroll
            for (int q = 0; q < 4; q++) acc[t][j][q] = 0.0f;

#pragma unroll
    for (int s = 0; s < GSTAGES - 1; s++) {
        uint32_t base = sb + s * G_STAGE_BYTES;
        g_load_stage(base, base + G_TILE_BYTES, s * GBK, g_a16, W, m0, wn0, tid);
        cp_commit();
    }

    for (int k = 0; k < GK_ITERS; k++) {
        cp_wait<GSTAGES - 2>();
        __syncthreads();

        // Prefetch k+3 into stage (k+3)%4 == stage k-1, drained by this barrier.
        int kf = k + GSTAGES - 1;
        if (kf < GK_ITERS) {
            int sf = kf % GSTAGES;
            uint32_t base = sb + sf * G_STAGE_BYTES;
            g_load_stage(base, base + G_TILE_BYTES, kf * GBK, g_a16, W, m0, wn0, tid);
        }
        cp_commit();

        const int s = k % GSTAGES;
        const uint32_t sA = sb + s * G_STAGE_BYTES;
        const uint32_t sB = sA + G_TILE_BYTES;

#pragma unroll
        for (int ks = 0; ks < 2; ks++) {   // two k16 steps per GBK=32
            // A fragments: 2 m-tiles (16x16 each)
            uint32_t a[2][4];
#pragma unroll
            for (int t = 0; t < 2; t++) {
                int row = wm * 32 + t * 16 + (lane & 15);
                int c = ks * 2 + (lane >> 4);
                ldsm_x4(a[t][0], a[t][1], a[t][2], a[t][3], sA + tile_off16(row, c));
            }
            // B fragments: 8 n-tiles (8n x 16k); one x4 covers 2 n-tiles
            uint32_t b[8][2];
#pragma unroll
            for (int u = 0; u < 4; u++) {
                int nrow = wn * 64 + u * 16 + ((lane >> 4) << 3) + (lane & 7);
                int c = ks * 2 + ((lane >> 3) & 1);
                ldsm_x4(b[2 * u][0], b[2 * u][1], b[2 * u + 1][0], b[2 * u + 1][1],
                        sB + tile_off16(nrow, c));
            }
#pragma unroll
            for (int t = 0; t < 2; t++)
#pragma unroll
                for (int j = 0; j < 8; j++)
                    mma_f16(acc[t][j], a[t], b[j]);
        }
    }

    // Epilogue (acc layout: c0,c1 -> row g; c2,c3 -> row g+8; cols 2*tig..+1)
    const int g = lane >> 2;
    const int tig = lane & 3;
    if (is_proj) {
#pragma unroll
        for (int t = 0; t < 2; t++) {
            int row0 = m0 + wm * 32 + t * 16 + g;
            float mv0 = mask[row0] ? 0.0f : 0.125f;        // K^-0.5
            float mv1 = mask[row0 + 8] ? 0.0f : 0.125f;
#pragma unroll
            for (int j = 0; j < 8; j++) {
                int col = n0 + wn * 64 + j * 8 + tig * 2;
                int h = col >> 6, kk = col & 63;
                float b0 = g_bproj[col], b1 = g_bproj[col + 1];
                float p00 = acc[t][j][0] + b0, p01 = acc[t][j][1] + b1;
                float p10 = acc[t][j][2] + b0, p11 = acc[t][j][3] + b1;
                float s00, c00, s01, c01, s10, c10, s11, c11;
                sincosf(p00, &s00, &c00);
                sincosf(p01, &s01, &c01);
                sincosf(p10, &s10, &c10);
                sincosf(p11, &s11, &c11);
                size_t base0 = (size_t)row0 * 2048 + h * 128 + kk;
                size_t base1 = (size_t)(row0 + 8) * 2048 + h * 128 + kk;
                *(float2*)&g_phi[base0]      = make_float2(s00 * mv0, s01 * mv0);
                *(float2*)&g_phi[base0 + 64] = make_float2(c00 * mv0, c01 * mv0);
                *(float2*)&g_phi[base1]      = make_float2(s10 * mv1, s11 * mv1);
                *(float2*)&g_phi[base1 + 64] = make_float2(c10 * mv1, c11 * mv1);
            }
        }
    } else {
#pragma unroll
        for (int t = 0; t < 2; t++) {
            int row0 = m0 + wm * 32 + t * 16 + g;
#pragma unroll
            for (int j = 0; j < 8; j++) {
                int colw = wn0 + wn * 64 + j * 8 + tig * 2;
                float b0 = bv[colw], b1 = bv[colw + 1];
                float2 v0 = make_float2(acc[t][j][0] + b0, acc[t][j][1] + b1);
                float2 v1 = make_float2(acc[t][j][2] + b0, acc[t][j][3] + b1);
                *(float2*)&g_v[(size_t)row0 * 1024 + colw] = v0;
                *(float2*)&g_v[(size_t)(row0 + 8) * 1024 + colw] = v1;
            }
        }
    }
}

// ---------------------------------------------------------------------------
// Kernel 3: accumulate s, z — fp32x2 packed FFMA (exact fp32 numerics).
// ---------------------------------------------------------------------------
#define CHUNK 256

__global__ __launch_bounds__(256) void accum_kernel(float* __restrict__ out) {
    __shared__ float ps[16][128];
    __shared__ float vs[16][68];

    const int tid = threadIdx.x;
    const int bh = blockIdx.y;
    const int b = bh >> 4;
    const int h = bh & 15;
    const int sbeg = blockIdx.x * CHUNK;

    const int ty = tid >> 4;
    const int tx = tid & 15;

    unsigned long long acc2[4][4];
#pragma unroll
    for (int p = 0; p < 4; p++)
#pragma unroll
        for (int j = 0; j < 4; j++) acc2[p][j] = 0ull;
    float zacc = 0.0f;

    for (int sc = 0; sc < CHUNK; sc += 16) {
#pragma unroll
        for (int u = 0; u < 2; u++) {
            int i = tid + u * 256;
            int r = i >> 5, c4 = i & 31;
            size_t t = (size_t)(sbeg + sc + r) * B_SZ + b;
            *(float4*)&ps[r][c4 * 4] = *(const float4*)&g_phi[t * 2048 + h * 128 + c4 * 4];
        }
        {
            int r = tid >> 4, c4 = tid & 15;
            size_t t = (size_t)(sbeg + sc + r) * B_SZ + b;
            *(float4*)&vs[r][c4 * 4] = *(const float4*)&g_v[t * 1024 + h * 64 + c4 * 4];
        }
        __syncthreads();

#pragma unroll
        for (int r = 0; r < 16; r++) {
            unsigned long long a2[4];
#pragma unroll
            for (int p = 0; p < 4; p++)
                a2[p] = *(const unsigned long long*)&ps[r][ty * 8 + 2 * p];
            float4 bv4 = *(const float4*)&vs[r][tx * 4];
            unsigned long long bd[4];
            bd[0] = dup2(bv4.x); bd[1] = dup2(bv4.y);
            bd[2] = dup2(bv4.z); bd[3] = dup2(bv4.w);
#pragma unroll
            for (int p = 0; p < 4; p++)
#pragma unroll
                for (int j = 0; j < 4; j++)
                    ffma2(acc2[p][j], a2[p], bd[j]);
        }
        if (tid < 128) {
#pragma unroll
            for (int r = 0; r < 16; r++) zacc += ps[r][tid];
        }
        __syncthreads();
    }

    size_t sbase = (size_t)bh * 128 * 64;
#pragma unroll
    for (int p = 0; p < 4; p++) {
        int kk0 = ty * 8 + 2 * p;
#pragma unroll
        for (int j = 0; j < 4; j++) {
            float lo, hi;
            unpack2(acc2[p][j], lo, hi);
            atomicAdd(&out[OUT_S_OFF + sbase + (size_t)kk0 * 64 + tx * 4 + j], lo);
            atomicAdd(&out[OUT_S_OFF + sbase + (size_t)(kk0 + 1) * 64 + tx * 4 + j], hi);
        }
    }
    if (tid < 128) {
        atomicAdd(&out[OUT_Z_OFF + bh * 128 + tid], zacc);
    }
}

// ---------------------------------------------------------------------------
// Launch
// ---------------------------------------------------------------------------
extern "C" void kernel_launch(void* const* d_in, const int* in_sizes, int n_in,
                              void* d_out, int out_size) {
    (void)in_sizes; (void)n_in; (void)out_size;
    const float* enc  = (const float*)d_in[0];
    const float* Wk   = (const float*)d_in[1];
    const float* bk   = (const float*)d_in[2];
    const float* Wv   = (const float*)d_in[3];
    const float* bv   = (const float*)d_in[4];
    const float* rm   = (const float*)d_in[5];
    const unsigned char* mask = (const unsigned char*)d_in[6];
    float* out = (float*)d_out;

    cudaFuncSetAttribute(gemm_fused, cudaFuncAttributeMaxDynamicSharedMemorySize, G_SMEM_TOTAL);

    init_out_kernel<<<(OUT_TOTAL + 255) / 256, 256>>>(out, rm);

    // fp16 conversions (write __device__ symbols directly; no symbol lookup)
    convert_f16_kernel<<<1024, 256>>>(enc, 0, (int)((size_t)NTOK * E_DIM / 8));
    convert_f16_kernel<<<128, 256>>>(Wv, 1, E_DIM * E_DIM / 8);

    dim3 fgrid(H_NUM, E_DIM / 64);  // (16,16)
    fold_kernel<<<fgrid, 256>>>(Wk, bk, rm);

    dim3 ggrid(N2 / GBN, NTOK / GBM);   // (16, 256)
    gemm_fused<<<ggrid, 256, G_SMEM_TOTAL>>>(bv, mask);

    dim3 agrid(S_LEN / CHUNK, B_SZ * H_NUM);
    accum_kernel<<<agrid, 256>>>(out);
}

// round 11
// speedup vs baseline: 7.1416x; 1.2231x over previous
#include <cuda_runtime.h>
#include <cuda_fp16.h>
#include <math.h>
#include <stdint.h>

// Problem constants
#define S_LEN 4096
#define B_SZ  8
#define E_DIM 1024
#define H_NUM 16
#define D_DIM 64
#define K_DIM 64
#define TAU   1.0f
#define NTOK  (S_LEN * B_SZ)          // 32768
#define N2    (2 * E_DIM)             // 2048

// Output layout: s [B,H,2K,D] | z [B,H,2K] | rm [H,K,D]
#define OUT_S_OFF 0
#define OUT_Z_OFF 1048576
#define OUT_RM_OFF 1064960
#define OUT_TOTAL 1130496

// Scratch
__device__ __half g_phi16[(size_t)NTOK * 2048]; // [t][h*128+kk] fp16 (134 MB)
__device__ __half g_v16[(size_t)NTOK * 1024];   // [t][h*64+d]   fp16 (67 MB)
__device__ __half g_a16[(size_t)NTOK * E_DIM];  // enc fp16 (67 MB)
__device__ __half g_wp16[E_DIM * E_DIM];        // folded rm@Wk, fp16
__device__ __half g_wv16[E_DIM * E_DIM];        // Wv fp16
__device__ float  g_bproj[E_DIM];               // folded rm@bk (fp32)

// ---------------------------------------------------------------------------
// PTX helpers (arch-agnostic for compute_103 base)
// ---------------------------------------------------------------------------
__device__ __forceinline__ uint32_t smem_u32(const void* p) {
    uint32_t a;
    asm("{ .reg .u64 t; cvta.to.shared.u64 t, %1; cvt.u32.u64 %0, t; }" : "=r"(a) : "l"(p));
    return a;
}
__device__ __forceinline__ void cp_async16(uint32_t saddr, const void* g) {
    asm volatile("cp.async.cg.shared.global [%0], [%1], 16;" :: "r"(saddr), "l"(g));
}
__device__ __forceinline__ void cp_commit() { asm volatile("cp.async.commit_group;" ::: "memory"); }
template <int N> __device__ __forceinline__ void cp_wait() {
    asm volatile("cp.async.wait_group %0;" :: "n"(N) : "memory");
}
__device__ __forceinline__ void ldsm_x4(uint32_t& r0, uint32_t& r1, uint32_t& r2, uint32_t& r3,
                                        uint32_t addr) {
    asm volatile("ldmatrix.sync.aligned.m8n8.x4.shared.b16 {%0,%1,%2,%3}, [%4];"
                 : "=r"(r0), "=r"(r1), "=r"(r2), "=r"(r3) : "r"(addr));
}
__device__ __forceinline__ void ldsm_x4t(uint32_t& r0, uint32_t& r1, uint32_t& r2, uint32_t& r3,
                                         uint32_t addr) {
    asm volatile("ldmatrix.sync.aligned.m8n8.x4.trans.shared.b16 {%0,%1,%2,%3}, [%4];"
                 : "=r"(r0), "=r"(r1), "=r"(r2), "=r"(r3) : "r"(addr));
}
__device__ __forceinline__ void mma_f16(float* c, const uint32_t* a, const uint32_t* b) {
    asm volatile(
        "mma.sync.aligned.m16n8k16.row.col.f32.f16.f16.f32 "
        "{%0,%1,%2,%3}, {%4,%5,%6,%7}, {%8,%9}, {%0,%1,%2,%3};"
        : "+f"(c[0]), "+f"(c[1]), "+f"(c[2]), "+f"(c[3])
        : "r"(a[0]), "r"(a[1]), "r"(a[2]), "r"(a[3]), "r"(b[0]), "r"(b[1]));
}

// ---------------------------------------------------------------------------
// Kernel 0: init output — zero s,z; write rm/tau
// ---------------------------------------------------------------------------
__global__ void init_out_kernel(float* __restrict__ out, const float* __restrict__ rm_in) {
    int i = blockIdx.x * blockDim.x + threadIdx.x;
    if (i < OUT_RM_OFF) {
        out[i] = 0.0f;
    } else if (i < OUT_TOTAL) {
        out[i] = rm_in[i - OUT_RM_OFF] * (1.0f / TAU);
    }
}

// ---------------------------------------------------------------------------
// Kernel C: fp32 -> fp16 convert (dst selector: 0=g_a16, 1=g_wv16)
// ---------------------------------------------------------------------------
__global__ void convert_f16_kernel(const float* __restrict__ src, int which, int n8) {
    __half* dst = (which == 0) ? g_a16 : g_wv16;
    int stride = gridDim.x * blockDim.x;
    for (int i = blockIdx.x * blockDim.x + threadIdx.x; i < n8; i += stride) {
        const float4* s = (const float4*)(src + (size_t)i * 8);
        float4 v0 = s[0], v1 = s[1];
        __half2 h0 = __floats2half2_rn(v0.x, v0.y);
        __half2 h1 = __floats2half2_rn(v0.z, v0.w);
        __half2 h2 = __floats2half2_rn(v1.x, v1.y);
        __half2 h3 = __floats2half2_rn(v1.z, v1.w);
        uint4 pack;
        pack.x = *(uint32_t*)&h0;
        pack.y = *(uint32_t*)&h1;
        pack.z = *(uint32_t*)&h2;
        pack.w = *(uint32_t*)&h3;
        *(uint4*)(dst + (size_t)i * 8) = pack;
    }
}

// ---------------------------------------------------------------------------
// Kernel F: fold rm into Wk -> fp16 Wproj; fp32 bproj.
// ---------------------------------------------------------------------------
__global__ __launch_bounds__(256) void fold_kernel(
    const float* __restrict__ Wk, const float* __restrict__ bk,
    const float* __restrict__ rm) {
    __shared__ float rs[64][65];   // [kk][d]
    __shared__ float wks[64][65];  // [d][e]

    const int tid = threadIdx.x;
    const int h = blockIdx.x;
    const int e0 = blockIdx.y * 64;
    const float pscale = (0.125f / (TAU * TAU));

#pragma unroll
    for (int u = 0; u < 16; u++) {
        int i = tid + u * 256;
        rs[i >> 6][i & 63] = rm[h * 4096 + i];
    }
#pragma unroll
    for (int u = 0; u < 16; u++) {
        int i = tid + u * 256;
        int d = i >> 6, e = i & 63;
        wks[d][e] = Wk[(size_t)(h * 64 + d) * E_DIM + e0 + e];
    }
    __syncthreads();

    const int ty = tid >> 4;
    const int tx = tid & 15;
    float acc[4][4];
#pragma unroll
    for (int i = 0; i < 4; i++)
#pragma unroll
        for (int j = 0; j < 4; j++) acc[i][j] = 0.0f;
#pragma unroll
    for (int d = 0; d < 64; d++) {
        float a[4], b[4];
#pragma unroll
        for (int i = 0; i < 4; i++) a[i] = rs[ty * 4 + i][d];
#pragma unroll
        for (int j = 0; j < 4; j++) b[j] = wks[d][tx * 4 + j];
#pragma unroll
        for (int i = 0; i < 4; i++)
#pragma unroll
            for (int j = 0; j < 4; j++) acc[i][j] = fmaf(a[i], b[j], acc[i][j]);
    }
#pragma unroll
    for (int i = 0; i < 4; i++)
#pragma unroll
        for (int j = 0; j < 4; j++)
            g_wp16[(size_t)(h * 64 + ty * 4 + i) * E_DIM + e0 + tx * 4 + j] =
                __float2half_rn(acc[i][j] * pscale);

    if (blockIdx.y == 0 && tid < 64) {
        float s = 0.0f;
#pragma unroll
        for (int d = 0; d < 64; d++) s = fmaf(rs[tid][d], bk[h * 64 + d], s);
        g_bproj[h * 64 + tid] = s * pscale;
    }
}

// ---------------------------------------------------------------------------
// Kernel 1: fused GEMM on fp16 m16n8k16 mma.sync.
//   cols 0..1023   : proj -> sin/cos -> g_phi16 (fp16)
//   cols 1024..2047: v    -> g_v16 (fp16)
// ---------------------------------------------------------------------------
#define GBM 128
#define GBN 128
#define GBK 32
#define GSTAGES 4
#define GK_ITERS (E_DIM / GBK)                 // 32
#define G_TILE_BYTES (128 * GBK * 2)           // 8 KB (fp16)
#define G_STAGE_BYTES (2 * G_TILE_BYTES)       // 16 KB
#define G_SMEM_TOTAL (GSTAGES * G_STAGE_BYTES) // 64 KB

// byte offset in a [128 rows][32 fp16] tile; c = 16B chunk (0..3)
__device__ __forceinline__ uint32_t tile_off16(int r, int c) {
    return (uint32_t)(r * 64 + ((c ^ ((r >> 1) & 3)) << 4));
}

__device__ __forceinline__ void g_load_stage(uint32_t sA, uint32_t sB, int k0,
                                             const __half* __restrict__ A,
                                             const __half* __restrict__ W,
                                             int m0, int wn0, int tid) {
    const __half* ap = A + (size_t)m0 * E_DIM + k0;
    const __half* bp = W + (size_t)wn0 * E_DIM + k0;
#pragma unroll
    for (int i = 0; i < 2; i++) {
        int lin = tid + i * 256;
        int r = lin >> 2, c = lin & 3;
        cp_async16(sA + tile_off16(r, c), ap + (size_t)r * E_DIM + c * 8);
    }
#pragma unroll
    for (int i = 0; i < 2; i++) {
        int lin = tid + i * 256;
        int r = lin >> 2, c = lin & 3;
        cp_async16(sB + tile_off16(r, c), bp + (size_t)r * E_DIM + c * 8);
    }
}

__global__ __launch_bounds__(256) void gemm_fused(
    const float* __restrict__ bv,
    const unsigned char* __restrict__ mask) {
    extern __shared__ char smem[];
    const uint32_t sb = smem_u32(smem);

    const int tid = threadIdx.x;
    const int lane = tid & 31;
    const int warp = tid >> 5;
    const int wm = warp & 3;
    const int wn = warp >> 2;

    const int n0 = blockIdx.x * GBN;
    const int m0 = blockIdx.y * GBM;
    const bool is_proj = (n0 < E_DIM);
    const __half* __restrict__ W = is_proj ? g_wp16 : g_wv16;
    const int wn0 = n0 & (E_DIM - 1);

    float acc[2][8][4];
#pragma unroll
    for (int t = 0; t < 2; t++)
#pragma unroll
        for (int j = 0; j < 8; j++)
#pragma unroll
            for (int q = 0; q < 4; q++) acc[t][j][q] = 0.0f;

#pragma unroll
    for (int s = 0; s < GSTAGES - 1; s++) {
        uint32_t base = sb + s * G_STAGE_BYTES;
        g_load_stage(base, base + G_TILE_BYTES, s * GBK, g_a16, W, m0, wn0, tid);
        cp_commit();
    }

    for (int k = 0; k < GK_ITERS; k++) {
        cp_wait<GSTAGES - 2>();
        __syncthreads();

        int kf = k + GSTAGES - 1;
        if (kf < GK_ITERS) {
            int sf = kf % GSTAGES;
            uint32_t base = sb + sf * G_STAGE_BYTES;
            g_load_stage(base, base + G_TILE_BYTES, kf * GBK, g_a16, W, m0, wn0, tid);
        }
        cp_commit();

        const int s = k % GSTAGES;
        const uint32_t sA = sb + s * G_STAGE_BYTES;
        const uint32_t sB = sA + G_TILE_BYTES;

#pragma unroll
        for (int ks = 0; ks < 2; ks++) {
            uint32_t a[2][4];
#pragma unroll
            for (int t = 0; t < 2; t++) {
                int row = wm * 32 + t * 16 + (lane & 15);
                int c = ks * 2 + (lane >> 4);
                ldsm_x4(a[t][0], a[t][1], a[t][2], a[t][3], sA + tile_off16(row, c));
            }
            uint32_t b[8][2];
#pragma unroll
            for (int u = 0; u < 4; u++) {
                int nrow = wn * 64 + u * 16 + ((lane >> 4) << 3) + (lane & 7);
                int c = ks * 2 + ((lane >> 3) & 1);
                ldsm_x4(b[2 * u][0], b[2 * u][1], b[2 * u + 1][0], b[2 * u + 1][1],
                        sB + tile_off16(nrow, c));
            }
#pragma unroll
            for (int t = 0; t < 2; t++)
#pragma unroll
                for (int j = 0; j < 8; j++)
                    mma_f16(acc[t][j], a[t], b[j]);
        }
    }

    // Epilogue -> fp16 outputs
    const int g = lane >> 2;
    const int tig = lane & 3;
    if (is_proj) {
#pragma unroll
        for (int t = 0; t < 2; t++) {
            int row0 = m0 + wm * 32 + t * 16 + g;
            float mv0 = mask[row0] ? 0.0f : 0.125f;        // K^-0.5
            float mv1 = mask[row0 + 8] ? 0.0f : 0.125f;
#pragma unroll
            for (int j = 0; j < 8; j++) {
                int col = n0 + wn * 64 + j * 8 + tig * 2;
                int h = col >> 6, kk = col & 63;
                float b0 = g_bproj[col], b1 = g_bproj[col + 1];
                float p00 = acc[t][j][0] + b0, p01 = acc[t][j][1] + b1;
                float p10 = acc[t][j][2] + b0, p11 = acc[t][j][3] + b1;
                float s00, c00, s01, c01, s10, c10, s11, c11;
                sincosf(p00, &s00, &c00);
                sincosf(p01, &s01, &c01);
                sincosf(p10, &s10, &c10);
                sincosf(p11, &s11, &c11);
                size_t base0 = (size_t)row0 * 2048 + h * 128 + kk;
                size_t base1 = (size_t)(row0 + 8) * 2048 + h * 128 + kk;
                *(__half2*)&g_phi16[base0]      = __floats2half2_rn(s00 * mv0, s01 * mv0);
                *(__half2*)&g_phi16[base0 + 64] = __floats2half2_rn(c00 * mv0, c01 * mv0);
                *(__half2*)&g_phi16[base1]      = __floats2half2_rn(s10 * mv1, s11 * mv1);
                *(__half2*)&g_phi16[base1 + 64] = __floats2half2_rn(c10 * mv1, c11 * mv1);
            }
        }
    } else {
#pragma unroll
        for (int t = 0; t < 2; t++) {
            int row0 = m0 + wm * 32 + t * 16 + g;
#pragma unroll
            for (int j = 0; j < 8; j++) {
                int colw = wn0 + wn * 64 + j * 8 + tig * 2;
                float b0 = bv[colw], b1 = bv[colw + 1];
                *(__half2*)&g_v16[(size_t)row0 * 1024 + colw] =
                    __floats2half2_rn(acc[t][j][0] + b0, acc[t][j][1] + b1);
                *(__half2*)&g_v16[(size_t)(row0 + 8) * 1024 + colw] =
                    __floats2half2_rn(acc[t][j][2] + b0, acc[t][j][3] + b1);
            }
        }
    }
}

// ---------------------------------------------------------------------------
// Kernel 3: accumulate s, z via fp16 tensor cores.
//   Per (b,h): s[128kk][64d] = sum_s phi[s][kk] * v[s][d].
//   Both operands stored [s][.] -> trans ldmatrix supplies [.][s] fragments.
//   Grid (8 seq-chunks of 512, 128 bh). 256 thr; warp grid 4(kk) x 2(d).
// ---------------------------------------------------------------------------
#define ACH 512
#define ANIT (ACH / 32)   // 16 iterations of 32 seq positions

// phi stage: 32 rows x 256B (16 chunks); v stage: 32 rows x 128B (8 chunks)
#define APHI_BYTES (32 * 256)
#define AV_BYTES   (32 * 128)
#define ABUF_BYTES (APHI_BYTES + AV_BYTES)   // 12 KB per buffer

__device__ __forceinline__ uint32_t aphi_off(int s, int c) {
    return (uint32_t)(s * 256 + ((c ^ (s & 7)) << 4));
}
__device__ __forceinline__ uint32_t av_off(int s, int c) {
    return (uint32_t)(s * 128 + ((c ^ (s & 7)) << 4));
}

__global__ __launch_bounds__(256) void accum_kernel(float* __restrict__ out) {
    __shared__ char asmem[2 * ABUF_BYTES];
    const uint32_t sb = smem_u32(asmem);

    const int tid = threadIdx.x;
    const int lane = tid & 31;
    const int warp = tid >> 5;
    const int wm = warp & 3;    // kk group: kk0 = wm*32
    const int wd = warp >> 2;   // d group:  d0 = wd*32

    const int bh = blockIdx.y;
    const int b = bh >> 4;
    const int h = bh & 15;
    const int sbeg = blockIdx.x * ACH;

    float acc[2][4][4];
#pragma unroll
    for (int t = 0; t < 2; t++)
#pragma unroll
        for (int j = 0; j < 4; j++)
#pragma unroll
            for (int q = 0; q < 4; q++) acc[t][j][q] = 0.0f;
    float z0 = 0.0f, z1 = 0.0f;

    // stage loader: 32 seq rows into buffer `buf`
    auto load32 = [&](int buf, int it) {
        uint32_t pb = sb + buf * ABUF_BYTES;
        uint32_t vb = pb + APHI_BYTES;
        int s_abs0 = sbeg + it * 32;
        // phi: 512 chunks of 16B
#pragma unroll
        for (int i = 0; i < 2; i++) {
            int lin = tid + i * 256;
            int r = lin >> 4, c = lin & 15;
            size_t t_tok = (size_t)(s_abs0 + r) * B_SZ + b;
            cp_async16(pb + aphi_off(r, c), g_phi16 + t_tok * 2048 + h * 128 + c * 8);
        }
        // v: 256 chunks
        {
            int r = tid >> 3, c = tid & 7;
            size_t t_tok = (size_t)(s_abs0 + r) * B_SZ + b;
            cp_async16(vb + av_off(r, c), g_v16 + t_tok * 1024 + h * 64 + c * 8);
        }
    };

    load32(0, 0);
    cp_commit();

    for (int it = 0; it < ANIT; it++) {
        cp_wait<0>();
        __syncthreads();
        if (it + 1 < ANIT) load32((it + 1) & 1, it + 1);
        cp_commit();

        const uint32_t pb = sb + (it & 1) * ABUF_BYTES;
        const uint32_t vb = pb + APHI_BYTES;

#pragma unroll
        for (int ks = 0; ks < 2; ks++) {   // two k16 steps (32 s)
            const int s_base = ks * 16;
            // A = phi^T fragments (m=kk, k=s):
            //   lane -> s_row = s_base + ((lane>>4)<<3) + (lane&7)
            //        -> chunk = kkbase/8 + ((lane>>3)&1)
            uint32_t a[2][4];
#pragma unroll
            for (int t = 0; t < 2; t++) {
                int srow = s_base + ((lane >> 4) << 3) + (lane & 7);
                int c = wm * 4 + t * 2 + ((lane >> 3) & 1);
                ldsm_x4t(a[t][0], a[t][1], a[t][2], a[t][3], pb + aphi_off(srow, c));
            }
            // B = v^T fragments (n=d, k=s):
            //   lane -> s_row = s_base + (((lane>>3)&1)<<3) + (lane&7)
            //        -> chunk = dbase/8 + (lane>>4)
            uint32_t bfr[4][2];
#pragma unroll
            for (int u = 0; u < 2; u++) {
                int srow = s_base + (((lane >> 3) & 1) << 3) + (lane & 7);
                int c = wd * 4 + u * 2 + (lane >> 4);
                uint32_t r0, r1, r2, r3;
                ldsm_x4t(r0, r1, r2, r3, vb + av_off(srow, c));
                bfr[2 * u][0] = r0; bfr[2 * u][1] = r1;       // n-tile d0-7
                bfr[2 * u + 1][0] = r2; bfr[2 * u + 1][1] = r3; // n-tile d8-15
            }
#pragma unroll
            for (int t = 0; t < 2; t++)
#pragma unroll
                for (int j = 0; j < 4; j++)
                    mma_f16(acc[t][j], a[t], bfr[j]);
        }

        // z: thread owns kk pair p = tid&63 over 8 seq rows (rowgrp = tid>>6)
        {
            int p = tid & 63;
            int rg = tid >> 6;
            int c = p >> 2;
            int sub = (p & 3) * 4;
#pragma unroll
            for (int i = 0; i < 8; i++) {
                int s = rg * 8 + i;
                uint32_t u;
                asm volatile("ld.shared.b32 %0, [%1];" : "=r"(u)
                             : "r"(pb + aphi_off(s, c) + sub));
                __half2 hv = *(__half2*)&u;
                z0 += __low2float(hv);
                z1 += __high2float(hv);
            }
        }
        __syncthreads();
    }

    // Commit s via atomics. Fragment c: rows g, g+8; cols tig*2, +1.
    const int g = lane >> 2;
    const int tig = lane & 3;
    size_t sbase = (size_t)bh * 128 * 64;
#pragma unroll
    for (int t = 0; t < 2; t++) {
        int kk0 = wm * 32 + t * 16 + g;
#pragma unroll
        for (int j = 0; j < 4; j++) {
            int d0 = wd * 32 + j * 8 + tig * 2;
            atomicAdd(&out[OUT_S_OFF + sbase + (size_t)kk0 * 64 + d0], acc[t][j][0]);
            atomicAdd(&out[OUT_S_OFF + sbase + (size_t)kk0 * 64 + d0 + 1], acc[t][j][1]);
            atomicAdd(&out[OUT_S_OFF + sbase + (size_t)(kk0 + 8) * 64 + d0], acc[t][j][2]);
            atomicAdd(&out[OUT_S_OFF + sbase + (size_t)(kk0 + 8) * 64 + d0 + 1], acc[t][j][3]);
        }
    }
    {
        int p = tid & 63;
        atomicAdd(&out[OUT_Z_OFF + bh * 128 + 2 * p], z0);
        atomicAdd(&out[OUT_Z_OFF + bh * 128 + 2 * p + 1], z1);
    }
}

// ---------------------------------------------------------------------------
// Launch
// ---------------------------------------------------------------------------
extern "C" void kernel_launch(void* const* d_in, const int* in_sizes, int n_in,
                              void* d_out, int out_size) {
    (void)in_sizes; (void)n_in; (void)out_size;
    const float* enc  = (const float*)d_in[0];
    const float* Wk   = (const float*)d_in[1];
    const float* bk   = (const float*)d_in[2];
    const float* Wv   = (const float*)d_in[3];
    const float* bv   = (const float*)d_in[4];
    const float* rm   = (const float*)d_in[5];
    const unsigned char* mask = (const unsigned char*)d_in[6];
    float* out = (float*)d_out;

    cudaFuncSetAttribute(gemm_fused, cudaFuncAttributeMaxDynamicSharedMemorySize, G_SMEM_TOTAL);

    init_out_kernel<<<(OUT_TOTAL + 255) / 256, 256>>>(out, rm);

    convert_f16_kernel<<<1024, 256>>>(enc, 0, (int)((size_t)NTOK * E_DIM / 8));
    convert_f16_kernel<<<128, 256>>>(Wv, 1, E_DIM * E_DIM / 8);

    dim3 fgrid(H_NUM, E_DIM / 64);  // (16,16)
    fold_kernel<<<fgrid, 256>>>(Wk, bk, rm);

    dim3 ggrid(N2 / GBN, NTOK / GBM);   // (16, 256)
    gemm_fused<<<ggrid, 256, G_SMEM_TOTAL>>>(bv, mask);

    dim3 agrid(S_LEN / ACH, B_SZ * H_NUM);  // (8, 128)
    accum_kernel<<<agrid, 256>>>(out);
}

// round 12
// speedup vs baseline: 7.5734x; 1.0605x over previous
#include <cuda_runtime.h>
#include <cuda_fp16.h>
#include <math.h>
#include <stdint.h>

// Problem constants
#define S_LEN 4096
#define B_SZ  8
#define E_DIM 1024
#define H_NUM 16
#define D_DIM 64
#define K_DIM 64
#define TAU   1.0f
#define NTOK  (S_LEN * B_SZ)          // 32768
#define N2    (2 * E_DIM)             // 2048

// Output layout: s [B,H,2K,D] | z [B,H,2K] | rm [H,K,D]
#define OUT_S_OFF 0
#define OUT_Z_OFF 1048576
#define OUT_RM_OFF 1064960
#define OUT_TOTAL 1130496

// Scratch
__device__ __half g_phi16[(size_t)NTOK * 2048]; // [t][h*128+kk] fp16 (134 MB)
__device__ __half g_v16[(size_t)NTOK * 1024];   // [t][h*64+d]   fp16 (67 MB)
__device__ __half g_a16[(size_t)NTOK * E_DIM];  // enc fp16 (67 MB)
__device__ __half g_wp16[E_DIM * E_DIM];        // folded rm@Wk, fp16
__device__ __half g_wv16[E_DIM * E_DIM];        // Wv fp16
__device__ float  g_bproj[E_DIM];               // folded rm@bk (fp32)

// ---------------------------------------------------------------------------
// PTX helpers (arch-agnostic for compute_103 base)
// ---------------------------------------------------------------------------
__device__ __forceinline__ uint32_t smem_u32(const void* p) {
    uint32_t a;
    asm("{ .reg .u64 t; cvta.to.shared.u64 t, %1; cvt.u32.u64 %0, t; }" : "=r"(a) : "l"(p));
    return a;
}
__device__ __forceinline__ void cp_async16(uint32_t saddr, const void* g) {
    asm volatile("cp.async.cg.shared.global [%0], [%1], 16;" :: "r"(saddr), "l"(g));
}
__device__ __forceinline__ void cp_commit() { asm volatile("cp.async.commit_group;" ::: "memory"); }
template <int N> __device__ __forceinline__ void cp_wait() {
    asm volatile("cp.async.wait_group %0;" :: "n"(N) : "memory");
}
__device__ __forceinline__ void ldsm_x4(uint32_t& r0, uint32_t& r1, uint32_t& r2, uint32_t& r3,
                                        uint32_t addr) {
    asm volatile("ldmatrix.sync.aligned.m8n8.x4.shared.b16 {%0,%1,%2,%3}, [%4];"
                 : "=r"(r0), "=r"(r1), "=r"(r2), "=r"(r3) : "r"(addr));
}
__device__ __forceinline__ void ldsm_x4t(uint32_t& r0, uint32_t& r1, uint32_t& r2, uint32_t& r3,
                                         uint32_t addr) {
    asm volatile("ldmatrix.sync.aligned.m8n8.x4.trans.shared.b16 {%0,%1,%2,%3}, [%4];"
                 : "=r"(r0), "=r"(r1), "=r"(r2), "=r"(r3) : "r"(addr));
}
__device__ __forceinline__ void mma_f16(float* c, const uint32_t* a, const uint32_t* b) {
    asm volatile(
        "mma.sync.aligned.m16n8k16.row.col.f32.f16.f16.f32 "
        "{%0,%1,%2,%3}, {%4,%5,%6,%7}, {%8,%9}, {%0,%1,%2,%3};"
        : "+f"(c[0]), "+f"(c[1]), "+f"(c[2]), "+f"(c[3])
        : "r"(a[0]), "r"(a[1]), "r"(a[2]), "r"(a[3]), "r"(b[0]), "r"(b[1]));
}

// ---------------------------------------------------------------------------
// Kernel 0: init output — write rm/tau only (s,z fully written by accum)
// ---------------------------------------------------------------------------
__global__ void init_out_kernel(float* __restrict__ out, const float* __restrict__ rm_in) {
    int i = blockIdx.x * blockDim.x + threadIdx.x;
    if (i < OUT_TOTAL - OUT_RM_OFF) {
        out[OUT_RM_OFF + i] = rm_in[i] * (1.0f / TAU);
    }
}

// ---------------------------------------------------------------------------
// Kernel C: fp32 -> fp16 convert (dst selector: 0=g_a16, 1=g_wv16)
// ---------------------------------------------------------------------------
__global__ void convert_f16_kernel(const float* __restrict__ src, int which, int n8) {
    __half* dst = (which == 0) ? g_a16 : g_wv16;
    int stride = gridDim.x * blockDim.x;
    for (int i = blockIdx.x * blockDim.x + threadIdx.x; i < n8; i += stride) {
        const float4* s = (const float4*)(src + (size_t)i * 8);
        float4 v0 = s[0], v1 = s[1];
        __half2 h0 = __floats2half2_rn(v0.x, v0.y);
        __half2 h1 = __floats2half2_rn(v0.z, v0.w);
        __half2 h2 = __floats2half2_rn(v1.x, v1.y);
        __half2 h3 = __floats2half2_rn(v1.z, v1.w);
        uint4 pack;
        pack.x = *(uint32_t*)&h0;
        pack.y = *(uint32_t*)&h1;
        pack.z = *(uint32_t*)&h2;
        pack.w = *(uint32_t*)&h3;
        *(uint4*)(dst + (size_t)i * 8) = pack;
    }
}

// ---------------------------------------------------------------------------
// Kernel F: fold rm into Wk -> fp16 Wproj; fp32 bproj.
// ---------------------------------------------------------------------------
__global__ __launch_bounds__(256) void fold_kernel(
    const float* __restrict__ Wk, const float* __restrict__ bk,
    const float* __restrict__ rm) {
    __shared__ float rs[64][65];   // [kk][d]
    __shared__ float wks[64][65];  // [d][e]

    const int tid = threadIdx.x;
    const int h = blockIdx.x;
    const int e0 = blockIdx.y * 64;
    const float pscale = (0.125f / (TAU * TAU));

#pragma unroll
    for (int u = 0; u < 16; u++) {
        int i = tid + u * 256;
        rs[i >> 6][i & 63] = rm[h * 4096 + i];
    }
#pragma unroll
    for (int u = 0; u < 16; u++) {
        int i = tid + u * 256;
        int d = i >> 6, e = i & 63;
        wks[d][e] = Wk[(size_t)(h * 64 + d) * E_DIM + e0 + e];
    }
    __syncthreads();

    const int ty = tid >> 4;
    const int tx = tid & 15;
    float acc[4][4];
#pragma unroll
    for (int i = 0; i < 4; i++)
#pragma unroll
        for (int j = 0; j < 4; j++) acc[i][j] = 0.0f;
#pragma unroll
    for (int d = 0; d < 64; d++) {
        float a[4], b[4];
#pragma unroll
        for (int i = 0; i < 4; i++) a[i] = rs[ty * 4 + i][d];
#pragma unroll
        for (int j = 0; j < 4; j++) b[j] = wks[d][tx * 4 + j];
#pragma unroll
        for (int i = 0; i < 4; i++)
#pragma unroll
            for (int j = 0; j < 4; j++) acc[i][j] = fmaf(a[i], b[j], acc[i][j]);
    }
#pragma unroll
    for (int i = 0; i < 4; i++)
#pragma unroll
        for (int j = 0; j < 4; j++)
            g_wp16[(size_t)(h * 64 + ty * 4 + i) * E_DIM + e0 + tx * 4 + j] =
                __float2half_rn(acc[i][j] * pscale);

    if (blockIdx.y == 0 && tid < 64) {
        float s = 0.0f;
#pragma unroll
        for (int d = 0; d < 64; d++) s = fmaf(rs[tid][d], bk[h * 64 + d], s);
        g_bproj[h * 64 + tid] = s * pscale;
    }
}

// ---------------------------------------------------------------------------
// Kernel 1: fused GEMM on fp16 m16n8k16 mma.sync.
//   CTA 128x128x64, 3-stage cp.async (96 KB), 16 k-iters (half the barriers).
//   Tiles are [128 rows][64 fp16] = 128B rows, XOR-8 swizzle.
// ---------------------------------------------------------------------------
#define GBM 128
#define GBN 128
#define GBK 64
#define GSTAGES 3
#define GK_ITERS (E_DIM / GBK)                 // 16
#define G_TILE_BYTES (128 * GBK * 2)           // 16 KB (fp16)
#define G_STAGE_BYTES (2 * G_TILE_BYTES)       // 32 KB
#define G_SMEM_TOTAL (GSTAGES * G_STAGE_BYTES) // 96 KB

// byte offset in a [128 rows][64 fp16] tile; c = 16B chunk (0..7)
__device__ __forceinline__ uint32_t tile_off16(int r, int c) {
    return (uint32_t)(r * 128 + ((c ^ (r & 7)) << 4));
}

__device__ __forceinline__ void g_load_stage(uint32_t sA, uint32_t sB, int k0,
                                             const __half* __restrict__ A,
                                             const __half* __restrict__ W,
                                             int m0, int wn0, int tid) {
    const __half* ap = A + (size_t)m0 * E_DIM + k0;
    const __half* bp = W + (size_t)wn0 * E_DIM + k0;
#pragma unroll
    for (int i = 0; i < 4; i++) {   // A: 128 rows x 8 chunks = 1024
        int lin = tid + i * 256;
        int r = lin >> 3, c = lin & 7;
        cp_async16(sA + tile_off16(r, c), ap + (size_t)r * E_DIM + c * 8);
    }
#pragma unroll
    for (int i = 0; i < 4; i++) {
        int lin = tid + i * 256;
        int r = lin >> 3, c = lin & 7;
        cp_async16(sB + tile_off16(r, c), bp + (size_t)r * E_DIM + c * 8);
    }
}

__global__ __launch_bounds__(256) void gemm_fused(
    const float* __restrict__ bv,
    const unsigned char* __restrict__ mask) {
    extern __shared__ char smem[];
    const uint32_t sb = smem_u32(smem);

    const int tid = threadIdx.x;
    const int lane = tid & 31;
    const int warp = tid >> 5;
    const int wm = warp & 3;
    const int wn = warp >> 2;

    const int n0 = blockIdx.x * GBN;
    const int m0 = blockIdx.y * GBM;
    const bool is_proj = (n0 < E_DIM);
    const __half* __restrict__ W = is_proj ? g_wp16 : g_wv16;
    const int wn0 = n0 & (E_DIM - 1);

    float acc[2][8][4];
#pragma unroll
    for (int t = 0; t < 2; t++)
#pragma unroll
        for (int j = 0; j < 8; j++)
#pragma unroll
            for (int q = 0; q < 4; q++) acc[t][j][q] = 0.0f;

#pragma unroll
    for (int s = 0; s < GSTAGES - 1; s++) {
        uint32_t base = sb + s * G_STAGE_BYTES;
        g_load_stage(base, base + G_TILE_BYTES, s * GBK, g_a16, W, m0, wn0, tid);
        cp_commit();
    }

    for (int k = 0; k < GK_ITERS; k++) {
        cp_wait<1>();
        __syncthreads();

        // Prefetch k+2 into stage (k+2)%3 == stage k-1, drained by this barrier.
        int kf = k + 2;
        if (kf < GK_ITERS) {
            int sf = kf % GSTAGES;
            uint32_t base = sb + sf * G_STAGE_BYTES;
            g_load_stage(base, base + G_TILE_BYTES, kf * GBK, g_a16, W, m0, wn0, tid);
        }
        cp_commit();

        const int s = k % GSTAGES;
        const uint32_t sA = sb + s * G_STAGE_BYTES;
        const uint32_t sB = sA + G_TILE_BYTES;

#pragma unroll
        for (int ks = 0; ks < 4; ks++) {   // four k16 steps per GBK=64
            uint32_t a[2][4];
#pragma unroll
            for (int t = 0; t < 2; t++) {
                int row = wm * 32 + t * 16 + (lane & 15);
                int c = ks * 2 + (lane >> 4);
                ldsm_x4(a[t][0], a[t][1], a[t][2], a[t][3], sA + tile_off16(row, c));
            }
            uint32_t b[8][2];
#pragma unroll
            for (int u = 0; u < 4; u++) {
                int nrow = wn * 64 + u * 16 + ((lane >> 4) << 3) + (lane & 7);
                int c = ks * 2 + ((lane >> 3) & 1);
                ldsm_x4(b[2 * u][0], b[2 * u][1], b[2 * u + 1][0], b[2 * u + 1][1],
                        sB + tile_off16(nrow, c));
            }
#pragma unroll
            for (int t = 0; t < 2; t++)
#pragma unroll
                for (int j = 0; j < 8; j++)
                    mma_f16(acc[t][j], a[t], b[j]);
        }
    }

    // Epilogue -> fp16 outputs
    const int g = lane >> 2;
    const int tig = lane & 3;
    if (is_proj) {
#pragma unroll
        for (int t = 0; t < 2; t++) {
            int row0 = m0 + wm * 32 + t * 16 + g;
            float mv0 = mask[row0] ? 0.0f : 0.125f;        // K^-0.5
            float mv1 = mask[row0 + 8] ? 0.0f : 0.125f;
#pragma unroll
            for (int j = 0; j < 8; j++) {
                int col = n0 + wn * 64 + j * 8 + tig * 2;
                int h = col >> 6, kk = col & 63;
                float b0 = g_bproj[col], b1 = g_bproj[col + 1];
                float p00 = acc[t][j][0] + b0, p01 = acc[t][j][1] + b1;
                float p10 = acc[t][j][2] + b0, p11 = acc[t][j][3] + b1;
                float s00, c00, s01, c01, s10, c10, s11, c11;
                sincosf(p00, &s00, &c00);
                sincosf(p01, &s01, &c01);
                sincosf(p10, &s10, &c10);
                sincosf(p11, &s11, &c11);
                size_t base0 = (size_t)row0 * 2048 + h * 128 + kk;
                size_t base1 = (size_t)(row0 + 8) * 2048 + h * 128 + kk;
                *(__half2*)&g_phi16[base0]      = __floats2half2_rn(s00 * mv0, s01 * mv0);
                *(__half2*)&g_phi16[base0 + 64] = __floats2half2_rn(c00 * mv0, c01 * mv0);
                *(__half2*)&g_phi16[base1]      = __floats2half2_rn(s10 * mv1, s11 * mv1);
                *(__half2*)&g_phi16[base1 + 64] = __floats2half2_rn(c10 * mv1, c11 * mv1);
            }
        }
    } else {
#pragma unroll
        for (int t = 0; t < 2; t++) {
            int row0 = m0 + wm * 32 + t * 16 + g;
#pragma unroll
            for (int j = 0; j < 8; j++) {
                int colw = wn0 + wn * 64 + j * 8 + tig * 2;
                float b0 = bv[colw], b1 = bv[colw + 1];
                *(__half2*)&g_v16[(size_t)row0 * 1024 + colw] =
                    __floats2half2_rn(acc[t][j][0] + b0, acc[t][j][1] + b1);
                *(__half2*)&g_v16[(size_t)(row0 + 8) * 1024 + colw] =
                    __floats2half2_rn(acc[t][j][2] + b0, acc[t][j][3] + b1);
            }
        }
    }
}

// ---------------------------------------------------------------------------
// Kernel 3: accumulate s, z via fp16 tensor cores — ONE CTA per (b,h),
// full S=4096 reduction in registers -> plain stores (no atomics, no init).
// 128 CTAs = single wave. Warp grid 4(kk) x 2(d).
// ---------------------------------------------------------------------------
#define ANIT (S_LEN / 32)   // 128 iterations of 32 seq positions

// phi stage: 32 rows x 256B (16 chunks); v stage: 32 rows x 128B (8 chunks)
#define APHI_BYTES (32 * 256)
#define AV_BYTES   (32 * 128)
#define ABUF_BYTES (APHI_BYTES + AV_BYTES)   // 12 KB per buffer

__device__ __forceinline__ uint32_t aphi_off(int s, int c) {
    return (uint32_t)(s * 256 + ((c ^ (s & 7)) << 4));
}
__device__ __forceinline__ uint32_t av_off(int s, int c) {
    return (uint32_t)(s * 128 + ((c ^ (s & 7)) << 4));
}

__global__ __launch_bounds__(256) void accum_kernel(float* __restrict__ out) {
    __shared__ char asmem[2 * ABUF_BYTES];
    __shared__ float zred[4][128];
    const uint32_t sb = smem_u32(asmem);

    const int tid = threadIdx.x;
    const int lane = tid & 31;
    const int warp = tid >> 5;
    const int wm = warp & 3;    // kk group: kk0 = wm*32
    const int wd = warp >> 2;   // d group:  d0 = wd*32

    const int bh = blockIdx.x;
    const int b = bh >> 4;
    const int h = bh & 15;

    float acc[2][4][4];
#pragma unroll
    for (int t = 0; t < 2; t++)
#pragma unroll
        for (int j = 0; j < 4; j++)
#pragma unroll
            for (int q = 0; q < 4; q++) acc[t][j][q] = 0.0f;
    float z0 = 0.0f, z1 = 0.0f;

    auto load32 = [&](int buf, int it) {
        uint32_t pb = sb + buf * ABUF_BYTES;
        uint32_t vb = pb + APHI_BYTES;
        int s_abs0 = it * 32;
#pragma unroll
        for (int i = 0; i < 2; i++) {
            int lin = tid + i * 256;
            int r = lin >> 4, c = lin & 15;
            size_t t_tok = (size_t)(s_abs0 + r) * B_SZ + b;
            cp_async16(pb + aphi_off(r, c), g_phi16 + t_tok * 2048 + h * 128 + c * 8);
        }
        {
            int r = tid >> 3, c = tid & 7;
            size_t t_tok = (size_t)(s_abs0 + r) * B_SZ + b;
            cp_async16(vb + av_off(r, c), g_v16 + t_tok * 1024 + h * 64 + c * 8);
        }
    };

    load32(0, 0);
    cp_commit();

    for (int it = 0; it < ANIT; it++) {
        cp_wait<0>();
        __syncthreads();
        if (it + 1 < ANIT) load32((it + 1) & 1, it + 1);
        cp_commit();

        const uint32_t pb = sb + (it & 1) * ABUF_BYTES;
        const uint32_t vb = pb + APHI_BYTES;

#pragma unroll
        for (int ks = 0; ks < 2; ks++) {   // two k16 steps (32 s)
            const int s_base = ks * 16;
            uint32_t a[2][4];
#pragma unroll
            for (int t = 0; t < 2; t++) {
                int srow = s_base + ((lane >> 4) << 3) + (lane & 7);
                int c = wm * 4 + t * 2 + ((lane >> 3) & 1);
                ldsm_x4t(a[t][0], a[t][1], a[t][2], a[t][3], pb + aphi_off(srow, c));
            }
            uint32_t bfr[4][2];
#pragma unroll
            for (int u = 0; u < 2; u++) {
                int srow = s_base + (((lane >> 3) & 1) << 3) + (lane & 7);
                int c = wd * 4 + u * 2 + (lane >> 4);
                uint32_t r0, r1, r2, r3;
                ldsm_x4t(r0, r1, r2, r3, vb + av_off(srow, c));
                bfr[2 * u][0] = r0; bfr[2 * u][1] = r1;
                bfr[2 * u + 1][0] = r2; bfr[2 * u + 1][1] = r3;
            }
#pragma unroll
            for (int t = 0; t < 2; t++)
#pragma unroll
                for (int j = 0; j < 4; j++)
                    mma_f16(acc[t][j], a[t], bfr[j]);
        }

        // z sweep: thread owns kk pair p = tid&63 over 8 seq rows (rg = tid>>6)
        {
            int p = tid & 63;
            int rg = tid >> 6;
            int c = p >> 2;
            int sub = (p & 3) * 4;
#pragma unroll
            for (int i = 0; i < 8; i++) {
                int s = rg * 8 + i;
                uint32_t u;
                asm volatile("ld.shared.b32 %0, [%1];" : "=r"(u)
                             : "r"(pb + aphi_off(s, c) + sub));
                __half2 hv = *(__half2*)&u;
                z0 += __low2float(hv);
                z1 += __high2float(hv);
            }
        }
        __syncthreads();
    }

    // Commit s via plain stores (this CTA owns the whole (b,h) slice).
    const int g = lane >> 2;
    const int tig = lane & 3;
    size_t sbase = (size_t)bh * 128 * 64;
#pragma unroll
    for (int t = 0; t < 2; t++) {
        int kk0 = wm * 32 + t * 16 + g;
#pragma unroll
        for (int j = 0; j < 4; j++) {
            int d0 = wd * 32 + j * 8 + tig * 2;
            *(float2*)&out[OUT_S_OFF + sbase + (size_t)kk0 * 64 + d0] =
                make_float2(acc[t][j][0], acc[t][j][1]);
            *(float2*)&out[OUT_S_OFF + sbase + (size_t)(kk0 + 8) * 64 + d0] =
                make_float2(acc[t][j][2], acc[t][j][3]);
        }
    }
    // z reduce across the 4 row-groups, then plain store.
    {
        int p = tid & 63;
        int rg = tid >> 6;
        zred[rg][2 * p] = z0;
        zred[rg][2 * p + 1] = z1;
    }
    __syncthreads();
    if (tid < 128) {
        out[OUT_Z_OFF + bh * 128 + tid] =
            zred[0][tid] + zred[1][tid] + zred[2][tid] + zred[3][tid];
    }
}

// ---------------------------------------------------------------------------
// Launch
// ---------------------------------------------------------------------------
extern "C" void kernel_launch(void* const* d_in, const int* in_sizes, int n_in,
                              void* d_out, int out_size) {
    (void)in_sizes; (void)n_in; (void)out_size;
    const float* enc  = (const float*)d_in[0];
    const float* Wk   = (const float*)d_in[1];
    const float* bk   = (const float*)d_in[2];
    const float* Wv   = (const float*)d_in[3];
    const float* bv   = (const float*)d_in[4];
    const float* rm   = (const float*)d_in[5];
    const unsigned char* mask = (const unsigned char*)d_in[6];
    float* out = (float*)d_out;

    cudaFuncSetAttribute(gemm_fused, cudaFuncAttributeMaxDynamicSharedMemorySize, G_SMEM_TOTAL);

    init_out_kernel<<<((OUT_TOTAL - OUT_RM_OFF) + 255) / 256, 256>>>(out, rm);

    convert_f16_kernel<<<1024, 256>>>(enc, 0, (int)((size_t)NTOK * E_DIM / 8));
    convert_f16_kernel<<<128, 256>>>(Wv, 1, E_DIM * E_DIM / 8);

    dim3 fgrid(H_NUM, E_DIM / 64);  // (16,16)
    fold_kernel<<<fgrid, 256>>>(Wk, bk, rm);

    dim3 ggrid(N2 / GBN, NTOK / GBM);   // (16, 256)
    gemm_fused<<<ggrid, 256, G_SMEM_TOTAL>>>(bv, mask);

    accum_kernel<<<B_SZ * H_NUM, 256>>>(out);   // 128 CTAs, one per (b,h)
}